// round 1
// baseline (speedup 1.0000x reference)
#include <cuda_runtime.h>
#include <math.h>

// ---------------- problem constants ----------------
#define NU 100000
#define NM 20000
#define FU 32
#define FM 128
#define H1 8
#define C1 16
#define D1 128   // H1*C1
#define H2 4
#define C2 128
#define D2 512   // H2*C2
#define NE 250000
#define NEL 200000

// ---------------- device scratch (no runtime alloc allowed) ----------------
__device__ float    g_big  [(size_t)NU * D2];   // 204.8 MB: hs/hd scratch (100k side)
__device__ float    g_small[(size_t)NM * D2];   //  40.9 MB: hs/hd scratch (20k side)
__device__ float    g_zu1  [(size_t)NU * D1];
__device__ float    g_zm1  [(size_t)NM * D1];
__device__ float    g_zu2  [(size_t)NU * D2];
__device__ float    g_zm2  [(size_t)NM * D2];
__device__ float    g_ss   [NU * H1];           // per-src-node attention scores
__device__ float    g_sd   [NU * H1];           // per-dst-node attention scores
__device__ unsigned g_mx   [NU * H1];           // segment max (ordered-uint encoded)
__device__ float    g_sum  [NU * H1];           // segment sum of exp
__device__ float    g_ew   [NE * H1];           // per-edge e / exp values

// ---------------- helpers ----------------
__device__ __forceinline__ unsigned enc_f(float f) {
    unsigned u = __float_as_uint(f);
    return (u & 0x80000000u) ? ~u : (u | 0x80000000u);
}
__device__ __forceinline__ float dec_f(unsigned u) {
    return (u & 0x80000000u) ? __uint_as_float(u ^ 0x80000000u)
                             : __uint_as_float(~u);
}

// ---------------- GEMM: C[M,N] = A[M,K] @ B[K,N], K%16==0, N%64==0 ----------------
#define GBM 64
#define GBN 64
#define GBK 16
__global__ void gemm_kernel(const float* __restrict__ A, const float* __restrict__ B,
                            float* __restrict__ C, int M, int N, int K) {
    __shared__ float As[GBM][GBK + 1];
    __shared__ float Bs[GBK][GBN];
    const int tid = threadIdx.x;
    const int tx = tid & 15;
    const int ty = tid >> 4;
    const int row0 = blockIdx.y * GBM;
    const int col0 = blockIdx.x * GBN;

    float acc[4][4];
#pragma unroll
    for (int m = 0; m < 4; m++)
#pragma unroll
        for (int n = 0; n < 4; n++) acc[m][n] = 0.f;

    for (int k0 = 0; k0 < K; k0 += GBK) {
        // load A tile (zero-pad out-of-range rows)
#pragma unroll
        for (int i = tid; i < GBM * GBK; i += 256) {
            int r = i / GBK, k = i % GBK;
            int gr = row0 + r;
            As[r][k] = (gr < M) ? A[(size_t)gr * K + k0 + k] : 0.f;
        }
        // load B tile
#pragma unroll
        for (int i = tid; i < GBK * GBN; i += 256) {
            int k = i / GBN, c = i % GBN;
            Bs[k][c] = B[(size_t)(k0 + k) * N + col0 + c];
        }
        __syncthreads();
#pragma unroll
        for (int k = 0; k < GBK; k++) {
            float a[4], b[4];
#pragma unroll
            for (int m = 0; m < 4; m++) a[m] = As[ty * 4 + m][k];
#pragma unroll
            for (int n = 0; n < 4; n++) b[n] = Bs[k][tx * 4 + n];
#pragma unroll
            for (int m = 0; m < 4; m++)
#pragma unroll
                for (int n = 0; n < 4; n++) acc[m][n] += a[m] * b[n];
        }
        __syncthreads();
    }
#pragma unroll
    for (int m = 0; m < 4; m++) {
        int gr = row0 + ty * 4 + m;
        if (gr < M) {
#pragma unroll
            for (int n = 0; n < 4; n++)
                C[(size_t)gr * N + col0 + tx * 4 + n] = acc[m][n];
        }
    }
}

// ---------------- per-node attention score: s[n,h] = dot(h[n,h,:], a[h,:]) ----------------
__global__ void scores_kernel(const float* __restrict__ h, const float* __restrict__ a,
                              float* __restrict__ s, int N, int H, int C) {
    int warp = (blockIdx.x * blockDim.x + threadIdx.x) >> 5;
    int lane = threadIdx.x & 31;
    if (warp >= N * H) return;
    int n = warp / H, hh = warp % H;
    const float* hp = h + (size_t)n * H * C + hh * C;
    const float* ap = a + hh * C;
    float acc = 0.f;
    for (int c = lane; c < C; c += 32) acc += hp[c] * ap[c];
#pragma unroll
    for (int o = 16; o; o >>= 1) acc += __shfl_xor_sync(0xffffffffu, acc, o);
    if (lane == 0) s[warp] = acc;
}

// ---------------- init accumulators ----------------
__global__ void init_kernel(unsigned* __restrict__ mx, float* __restrict__ sum,
                            float* __restrict__ out, int nh, int nd) {
    int i = blockIdx.x * blockDim.x + threadIdx.x;
    if (i < nd) out[i] = 0.f;
    if (i < nh) { mx[i] = 0u; sum[i] = 0.f; }
}

// ---------------- edge pass 1: e = lrelu(ss[src]+sd[dst]); segment max ----------------
__global__ void edge_pass1(const int* __restrict__ src, const int* __restrict__ dst,
                           const float* __restrict__ ss, const float* __restrict__ sd,
                           float* __restrict__ ew, unsigned* __restrict__ mx,
                           int E, int H) {
    int i = blockIdx.x * blockDim.x + threadIdx.x;
    if (i >= E * H) return;
    int e = i / H, h = i % H;
    float v = ss[src[e] * H + h] + sd[dst[e] * H + h];
    v = (v > 0.f) ? v : 0.2f * v;
    ew[i] = v;
    atomicMax(&mx[dst[e] * H + h], enc_f(v));
}

// ---------------- edge pass 2: ex = exp(e - max); segment sum ----------------
__global__ void edge_pass2(const int* __restrict__ dst,
                           float* __restrict__ ew, const unsigned* __restrict__ mx,
                           float* __restrict__ sum, int E, int H) {
    int i = blockIdx.x * blockDim.x + threadIdx.x;
    if (i >= E * H) return;
    int e = i / H, h = i % H;
    float m = dec_f(mx[dst[e] * H + h]);
    float ex = expf(ew[i] - m);
    ew[i] = ex;
    atomicAdd(&sum[dst[e] * H + h], ex);
}

// ---------------- aggregation: out[dst] += ex * hs[src] (float4 granularity) ----------------
__global__ void aggregate_kernel(const int* __restrict__ src, const int* __restrict__ dst,
                                 const float* __restrict__ hs, const float* __restrict__ ew,
                                 float* __restrict__ out, int E, int H, int C) {
    int D4 = H * C / 4;
    int i = blockIdx.x * blockDim.x + threadIdx.x;
    if (i >= E * D4) return;
    int e = i / D4, q = i - e * D4;
    int d = q * 4;
    int h = d / C;
    float w = ew[e * H + h];
    float4 hv = *(const float4*)(hs + (size_t)src[e] * H * C + d);
    float* o = out + (size_t)dst[e] * H * C + d;
    atomicAdd(o + 0, w * hv.x);
    atomicAdd(o + 1, w * hv.y);
    atomicAdd(o + 2, w * hv.z);
    atomicAdd(o + 3, w * hv.w);
}

// ---------------- finalize: out = out/(sum+1e-16) + b, optional relu ----------------
__global__ void finalize_kernel(float* __restrict__ out, const float* __restrict__ sum,
                                const float* __restrict__ b, int Nd, int H, int C,
                                int do_relu) {
    int D = H * C;
    int i = blockIdx.x * blockDim.x + threadIdx.x;
    if (i >= Nd * D) return;
    int n = i / D, d = i - n * D;
    int h = d / C;
    float v = out[i] / (sum[n * H + h] + 1e-16f) + b[d];
    if (do_relu) v = fmaxf(v, 0.f);
    out[i] = v;
}

// ---------------- edge decoder: warp per label edge ----------------
__global__ void decoder_kernel(const float* __restrict__ zu2, const float* __restrict__ zm2,
                               const int* __restrict__ lu, const int* __restrict__ lm,
                               const float* __restrict__ dw1, const float* __restrict__ db1,
                               const float* __restrict__ dw2, const float* __restrict__ db2,
                               float* __restrict__ out, int EL) {
    int warp = (blockIdx.x * blockDim.x + threadIdx.x) >> 5;
    int lane = threadIdx.x & 31;
    if (warp >= EL) return;
    const float* zu = zu2 + (size_t)lu[warp] * D2;
    const float* zm = zm2 + (size_t)lm[warp] * D2;
    float acc[16];
#pragma unroll
    for (int j = 0; j < 16; j++) acc[j] = 0.f;
    for (int i = lane; i < 2 * D2; i += 32) {
        float z = (i < D2) ? zu[i] : zm[i - D2];
        const float* w = dw1 + (size_t)i * 16;
#pragma unroll
        for (int j = 0; j < 16; j++) acc[j] += z * __ldg(w + j);
    }
#pragma unroll
    for (int j = 0; j < 16; j++)
#pragma unroll
        for (int o = 16; o; o >>= 1) acc[j] += __shfl_xor_sync(0xffffffffu, acc[j], o);
    if (lane == 0) {
        float r = db2[0];
#pragma unroll
        for (int j = 0; j < 16; j++) {
            float hj = fmaxf(acc[j] + db1[j], 0.f);
            r += hj * dw2[j];
        }
        out[warp] = r;
    }
}

// ---------------- host-side GAT layer driver ----------------
static void run_gat(const float* x_src, int Ns, int Fs,
                    const float* x_dst, int Nd, int Fd,
                    const int* src, const int* dst,
                    const float* Ws, const float* Wd,
                    const float* a_s, const float* a_d, const float* b,
                    int H, int C, float* out, int do_relu,
                    float* hsbuf, float* hdbuf,
                    float* SS, float* SD, unsigned* MX, float* SUM, float* EW) {
    int D = H * C;
    dim3 g1(D / GBN, (Ns + GBM - 1) / GBM);
    gemm_kernel<<<g1, 256>>>(x_src, Ws, hsbuf, Ns, D, Fs);
    dim3 g2(D / GBN, (Nd + GBM - 1) / GBM);
    gemm_kernel<<<g2, 256>>>(x_dst, Wd, hdbuf, Nd, D, Fd);

    int nwarp_s = Ns * H, nwarp_d = Nd * H;
    scores_kernel<<<(nwarp_s * 32 + 255) / 256, 256>>>(hsbuf, a_s, SS, Ns, H, C);
    scores_kernel<<<(nwarp_d * 32 + 255) / 256, 256>>>(hdbuf, a_d, SD, Nd, H, C);

    int nd_total = Nd * D, nh_total = Nd * H;
    init_kernel<<<(nd_total + 255) / 256, 256>>>(MX, SUM, out, nh_total, nd_total);

    int eh = NE * H;
    edge_pass1<<<(eh + 255) / 256, 256>>>(src, dst, SS, SD, EW, MX, NE, H);
    edge_pass2<<<(eh + 255) / 256, 256>>>(dst, EW, MX, SUM, NE, H);

    int agg_total = NE * (D / 4);
    aggregate_kernel<<<(agg_total + 255) / 256, 256>>>(src, dst, hsbuf, EW, out, NE, H, C);

    finalize_kernel<<<(nd_total + 255) / 256, 256>>>(out, SUM, b, Nd, H, C, do_relu);
}

extern "C" void kernel_launch(void* const* d_in, const int* in_sizes, int n_in,
                              void* d_out, int out_size) {
    const float* xu     = (const float*)d_in[0];
    const float* xm     = (const float*)d_in[1];
    const int*   um_src = (const int*)d_in[2];
    const int*   um_dst = (const int*)d_in[3];
    const int*   mu_src = (const int*)d_in[4];
    const int*   mu_dst = (const int*)d_in[5];
    const int*   lab_u  = (const int*)d_in[6];
    const int*   lab_m  = (const int*)d_in[7];
    const float* w1um_s = (const float*)d_in[8];
    const float* w1um_d = (const float*)d_in[9];
    const float* a1um_s = (const float*)d_in[10];
    const float* a1um_d = (const float*)d_in[11];
    const float* b1um   = (const float*)d_in[12];
    const float* w1mu_s = (const float*)d_in[13];
    const float* w1mu_d = (const float*)d_in[14];
    const float* a1mu_s = (const float*)d_in[15];
    const float* a1mu_d = (const float*)d_in[16];
    const float* b1mu   = (const float*)d_in[17];
    const float* w2um_s = (const float*)d_in[18];
    const float* w2um_d = (const float*)d_in[19];
    const float* a2um_s = (const float*)d_in[20];
    const float* a2um_d = (const float*)d_in[21];
    const float* b2um   = (const float*)d_in[22];
    const float* w2mu_s = (const float*)d_in[23];
    const float* w2mu_d = (const float*)d_in[24];
    const float* a2mu_s = (const float*)d_in[25];
    const float* a2mu_d = (const float*)d_in[26];
    const float* b2mu   = (const float*)d_in[27];
    const float* dw1    = (const float*)d_in[28];
    const float* db1    = (const float*)d_in[29];
    const float* dw2    = (const float*)d_in[30];
    const float* db2    = (const float*)d_in[31];

    float *BIG, *SMALL, *ZU1, *ZM1, *ZU2, *ZM2, *SS, *SD, *SUM, *EW;
    unsigned* MX;
    cudaGetSymbolAddress((void**)&BIG,   g_big);
    cudaGetSymbolAddress((void**)&SMALL, g_small);
    cudaGetSymbolAddress((void**)&ZU1,   g_zu1);
    cudaGetSymbolAddress((void**)&ZM1,   g_zm1);
    cudaGetSymbolAddress((void**)&ZU2,   g_zu2);
    cudaGetSymbolAddress((void**)&ZM2,   g_zm2);
    cudaGetSymbolAddress((void**)&SS,    g_ss);
    cudaGetSymbolAddress((void**)&SD,    g_sd);
    cudaGetSymbolAddress((void**)&MX,    g_mx);
    cudaGetSymbolAddress((void**)&SUM,   g_sum);
    cudaGetSymbolAddress((void**)&EW,    g_ew);

    // ---- layer 1: zm = relu(GAT(xu -> xm)), zu = relu(GAT(xm -> xu)) ----
    run_gat(xu, NU, FU, xm, NM, FM, um_src, um_dst,
            w1um_s, w1um_d, a1um_s, a1um_d, b1um,
            H1, C1, ZM1, 1, BIG, SMALL, SS, SD, MX, SUM, EW);
    run_gat(xm, NM, FM, xu, NU, FU, mu_src, mu_dst,
            w1mu_s, w1mu_d, a1mu_s, a1mu_d, b1mu,
            H1, C1, ZU1, 1, SMALL, BIG, SS, SD, MX, SUM, EW);

    // ---- layer 2: zm2 = GAT(zu -> zm), zu2 = GAT(zm -> zu) ----
    run_gat(ZU1, NU, D1, ZM1, NM, D1, um_src, um_dst,
            w2um_s, w2um_d, a2um_s, a2um_d, b2um,
            H2, C2, ZM2, 0, BIG, SMALL, SS, SD, MX, SUM, EW);
    run_gat(ZM1, NM, D1, ZU1, NU, D1, mu_src, mu_dst,
            w2mu_s, w2mu_d, a2mu_s, a2mu_d, b2mu,
            H2, C2, ZU2, 0, SMALL, BIG, SS, SD, MX, SUM, EW);

    // ---- edge decoder ----
    decoder_kernel<<<(NEL + 7) / 8, 256>>>(ZU2, ZM2, lab_u, lab_m,
                                           dw1, db1, dw2, db2,
                                           (float*)d_out, NEL);
}

// round 2
// speedup vs baseline: 4.1156x; 4.1156x over previous
#include <cuda_runtime.h>
#include <math.h>

// ---------------- problem constants ----------------
#define NU 100000
#define NM 20000
#define FU 32
#define FM 128
#define H1 8
#define C1 16
#define D1 128   // H1*C1
#define H2 4
#define C2 128
#define D2 512   // H2*C2
#define NE 250000
#define NEL 200000

// ---------------- device scratch (no runtime alloc allowed) ----------------
__device__ float g_big  [(size_t)NU * D2];   // hs/hd scratch (100k side)
__device__ float g_small[(size_t)NM * D2];   // hs/hd scratch (20k side)
__device__ float g_zu1  [(size_t)NU * D1];
__device__ float g_zm1  [(size_t)NM * D1];
__device__ float g_zu2  [(size_t)NU * D2];
__device__ float g_zm2  [(size_t)NM * D2];
__device__ float g_ss   [NU * H1];           // per-src-node attention scores
__device__ float g_sd   [NU * H1];           // per-dst-node attention scores
__device__ float g_preu [(size_t)NU * 16];
__device__ float g_prem [(size_t)NM * 16];
// CSR per direction
__device__ int g_row_um[NM];
__device__ int g_cnt_um[NM];
__device__ int g_ssrc_um[NE];
__device__ int g_row_mu[NU];
__device__ int g_cnt_mu[NU];
__device__ int g_ssrc_mu[NE];
__device__ int g_bsum[128];

// ---------------- helpers ----------------
__device__ __forceinline__ unsigned enc_f(float f) {
    unsigned u = __float_as_uint(f);
    return (u & 0x80000000u) ? ~u : (u | 0x80000000u);
}
__device__ __forceinline__ float dec_f(unsigned u) {
    return (u & 0x80000000u) ? __uint_as_float(u ^ 0x80000000u)
                             : __uint_as_float(~u);
}

// ================= GEMM: C[M,N] = A[M,K] @ B[K,N]; N%128==0, K%8==0 =================
__global__ void __launch_bounds__(256, 2)
gemm128(const float* __restrict__ A, const float* __restrict__ B,
        float* __restrict__ C, int M, int N, int K) {
    __shared__ float As[2][8][128];
    __shared__ float Bs[2][8][128];
    const int tid = threadIdx.x;
    const int tx = tid & 15, ty = tid >> 4;
    const int row0 = blockIdx.y * 128, col0 = blockIdx.x * 128;
    const int ar = tid >> 1, ak = (tid & 1) * 4;   // A tile: 128 rows x 8 k
    const int bk = tid >> 5, bc = (tid & 31) * 4;  // B tile: 8 k x 128 cols

    float acc[8][8];
#pragma unroll
    for (int i = 0; i < 8; i++)
#pragma unroll
        for (int j = 0; j < 8; j++) acc[i][j] = 0.f;

    float4 aR, bR;
    // first tile load
    {
        int gr = row0 + ar;
        aR = make_float4(0.f, 0.f, 0.f, 0.f);
        if (gr < M) aR = *(const float4*)(A + (size_t)gr * K + ak);
        bR = *(const float4*)(B + (size_t)bk * N + col0 + bc);
        As[0][ak + 0][ar] = aR.x; As[0][ak + 1][ar] = aR.y;
        As[0][ak + 2][ar] = aR.z; As[0][ak + 3][ar] = aR.w;
        *(float4*)&Bs[0][bk][bc] = bR;
    }
    __syncthreads();

    const int nt = K >> 3;
    for (int t = 0; t < nt; t++) {
        if (t + 1 < nt) {
            int k0 = (t + 1) << 3;
            int gr = row0 + ar;
            aR = make_float4(0.f, 0.f, 0.f, 0.f);
            if (gr < M) aR = *(const float4*)(A + (size_t)gr * K + k0 + ak);
            bR = *(const float4*)(B + (size_t)(k0 + bk) * N + col0 + bc);
        }
        const int buf = t & 1;
#pragma unroll
        for (int kk = 0; kk < 8; kk++) {
            float a[8], b[8];
            *(float4*)(a)     = *(const float4*)&As[buf][kk][ty * 8];
            *(float4*)(a + 4) = *(const float4*)&As[buf][kk][ty * 8 + 4];
            *(float4*)(b)     = *(const float4*)&Bs[buf][kk][tx * 8];
            *(float4*)(b + 4) = *(const float4*)&Bs[buf][kk][tx * 8 + 4];
#pragma unroll
            for (int i = 0; i < 8; i++)
#pragma unroll
                for (int j = 0; j < 8; j++) acc[i][j] += a[i] * b[j];
        }
        if (t + 1 < nt) {
            const int nb = buf ^ 1;
            As[nb][ak + 0][ar] = aR.x; As[nb][ak + 1][ar] = aR.y;
            As[nb][ak + 2][ar] = aR.z; As[nb][ak + 3][ar] = aR.w;
            *(float4*)&Bs[nb][bk][bc] = bR;
            __syncthreads();
        }
    }
#pragma unroll
    for (int i = 0; i < 8; i++) {
        int gr = row0 + ty * 8 + i;
        if (gr < M) {
            float4 v0 = make_float4(acc[i][0], acc[i][1], acc[i][2], acc[i][3]);
            float4 v1 = make_float4(acc[i][4], acc[i][5], acc[i][6], acc[i][7]);
            *(float4*)(C + (size_t)gr * N + col0 + tx * 8)     = v0;
            *(float4*)(C + (size_t)gr * N + col0 + tx * 8 + 4) = v1;
        }
    }
}

// ================= per-node attention score =================
__global__ void scores_kernel(const float* __restrict__ h, const float* __restrict__ a,
                              float* __restrict__ s, int N, int H, int C) {
    int warp = (blockIdx.x * blockDim.x + threadIdx.x) >> 5;
    int lane = threadIdx.x & 31;
    if (warp >= N * H) return;
    int n = warp / H, hh = warp % H;
    const float* hp = h + (size_t)n * H * C + hh * C;
    const float* ap = a + hh * C;
    float acc = 0.f;
    for (int c = lane; c < C; c += 32) acc += hp[c] * ap[c];
#pragma unroll
    for (int o = 16; o; o >>= 1) acc += __shfl_xor_sync(0xffffffffu, acc, o);
    if (lane == 0) s[warp] = acc;
}

// ================= CSR build kernels =================
__global__ void zero_int(int* __restrict__ p, int n) {
    int i = blockIdx.x * blockDim.x + threadIdx.x;
    if (i < n) p[i] = 0;
}
__global__ void count_k(const int* __restrict__ dst, int* __restrict__ cnt, int E) {
    int i = blockIdx.x * blockDim.x + threadIdx.x;
    if (i < E) atomicAdd(&cnt[dst[i]], 1);
}
__global__ void scan_block(const int* __restrict__ cnt, int* __restrict__ row,
                           int* __restrict__ bsum, int n) {
    __shared__ int sh[1024];
    int i = blockIdx.x * 1024 + threadIdx.x;
    int v = (i < n) ? cnt[i] : 0;
    sh[threadIdx.x] = v;
    __syncthreads();
    for (int o = 1; o < 1024; o <<= 1) {
        int t = (threadIdx.x >= o) ? sh[threadIdx.x - o] : 0;
        __syncthreads();
        sh[threadIdx.x] += t;
        __syncthreads();
    }
    if (i < n) row[i] = sh[threadIdx.x] - v;           // exclusive
    if (threadIdx.x == 1023) bsum[blockIdx.x] = sh[1023];
}
__global__ void scan_bsum(int* __restrict__ bsum, int nb) {
    __shared__ int sh[128];
    int t = threadIdx.x;
    int v = (t < nb) ? bsum[t] : 0;
    sh[t] = v;
    __syncthreads();
    for (int o = 1; o < 128; o <<= 1) {
        int x = (t >= o) ? sh[t - o] : 0;
        __syncthreads();
        sh[t] += x;
        __syncthreads();
    }
    if (t < nb) bsum[t] = sh[t] - v;                   // exclusive
}
__global__ void add_off(int* __restrict__ row, const int* __restrict__ bsum, int n) {
    int i = blockIdx.x * 1024 + threadIdx.x;
    if (i < n) row[i] += bsum[blockIdx.x];
}
__global__ void scatter_k(const int* __restrict__ src, const int* __restrict__ dst,
                          const int* __restrict__ row, int* __restrict__ cur,
                          int* __restrict__ ssrc, int E) {
    int e = blockIdx.x * blockDim.x + threadIdx.x;
    if (e >= E) return;
    int d = dst[e];
    int pos = row[d] + atomicAdd(&cur[d], 1);
    ssrc[pos] = src[e];
}

// ================= fused softmax + aggregate + finalize (block per dst) =================
template <int H, int C>
__global__ void __launch_bounds__(128)
gat_agg(const float* __restrict__ hs, const float* __restrict__ ss,
        const float* __restrict__ sd, const int* __restrict__ row,
        const int* __restrict__ deg_, const int* __restrict__ ssrc,
        const float* __restrict__ b, float* __restrict__ out, int do_relu) {
    constexpr int D = H * C;
    constexpr int PC = D / 128;
    constexpr int CAP = 2048 / H;   // cached-alpha edge capacity (8KB)
    const int d = blockIdx.x;
    const int tid = threadIdx.x;
    const int start = row[d];
    const int deg = deg_[d];

    __shared__ unsigned smax[H];
    __shared__ float ssum[H];
    __shared__ float sdd[H];
    __shared__ float sal[2048];

    if (tid < H) { smax[tid] = 0u; ssum[tid] = 0.f; sdd[tid] = sd[d * H + tid]; }
    __syncthreads();

    // phase A: segment max over e = lrelu(ss[src]+sd[d])
    for (int i = tid; i < deg * H; i += 128) {
        int k = i / H, h = i - k * H;
        int s = ssrc[start + k];
        float v = ss[s * H + h] + sdd[h];
        v = (v > 0.f) ? v : 0.2f * v;
        atomicMax(&smax[h], enc_f(v));
    }
    __syncthreads();
    // phase B: exp + segment sum (cache exp values for small deg)
    for (int i = tid; i < deg * H; i += 128) {
        int k = i / H, h = i - k * H;
        int s = ssrc[start + k];
        float v = ss[s * H + h] + sdd[h];
        v = (v > 0.f) ? v : 0.2f * v;
        float ex = __expf(v - dec_f(smax[h]));
        if (k < CAP) sal[k * H + h] = ex;
        atomicAdd(&ssum[h], ex);
    }
    __syncthreads();
    // phase C: weighted aggregation, register accumulators
    float acc[PC];
#pragma unroll
    for (int j = 0; j < PC; j++) acc[j] = 0.f;
    for (int k = 0; k < deg; k++) {
        int s = ssrc[start + k];
        const float* hp = hs + (size_t)s * D;
#pragma unroll
        for (int j = 0; j < PC; j++) {
            int ch = tid + j * 128;
            int h = ch / C;
            float w;
            if (k < CAP) {
                w = sal[k * H + h];
            } else {
                float v = ss[s * H + h] + sdd[h];
                v = (v > 0.f) ? v : 0.2f * v;
                w = __expf(v - dec_f(smax[h]));
            }
            acc[j] += w * hp[ch];
        }
    }
#pragma unroll
    for (int j = 0; j < PC; j++) {
        int ch = tid + j * 128;
        int h = ch / C;
        float v = acc[j] / (ssum[h] + 1e-16f) + b[ch];
        if (do_relu) v = fmaxf(v, 0.f);
        out[(size_t)d * D + ch] = v;
    }
}

// ================= decoder: per-node partials, weights in shared =================
__global__ void __launch_bounds__(128)
pre_kernel(const float* __restrict__ z, const float* __restrict__ dw1,
           float* __restrict__ pre, int N, int roff) {
    __shared__ float sw[512 * 16];  // 32KB
    const int tid = threadIdx.x;
    for (int i = tid; i < 512 * 16; i += 128) sw[i] = dw1[(size_t)roff * 16 + i];
    __syncthreads();
    int n = blockIdx.x * 128 + tid;
    if (n >= N) return;
    const float4* zp = (const float4*)(z + (size_t)n * 512);
    float acc[16];
#pragma unroll
    for (int j = 0; j < 16; j++) acc[j] = 0.f;
    for (int kq = 0; kq < 128; kq++) {
        float4 zv = zp[kq];
        const float* w0 = &sw[(kq * 4 + 0) * 16];
        const float* w1 = &sw[(kq * 4 + 1) * 16];
        const float* w2 = &sw[(kq * 4 + 2) * 16];
        const float* w3 = &sw[(kq * 4 + 3) * 16];
#pragma unroll
        for (int j = 0; j < 16; j++)
            acc[j] += zv.x * w0[j] + zv.y * w1[j] + zv.z * w2[j] + zv.w * w3[j];
    }
#pragma unroll
    for (int j = 0; j < 16; j++) pre[(size_t)n * 16 + j] = acc[j];
}

__global__ void dec_final(const float* __restrict__ preu, const float* __restrict__ prem,
                          const int* __restrict__ lu, const int* __restrict__ lm,
                          const float* __restrict__ db1, const float* __restrict__ dw2,
                          const float* __restrict__ db2, float* __restrict__ out, int EL) {
    int i = blockIdx.x * blockDim.x + threadIdx.x;
    if (i >= EL) return;
    const float* pu = preu + (size_t)lu[i] * 16;
    const float* pm = prem + (size_t)lm[i] * 16;
    float r = db2[0];
#pragma unroll
    for (int j = 0; j < 16; j++) {
        float h = fmaxf(pu[j] + pm[j] + db1[j], 0.f);
        r += h * dw2[j];
    }
    out[i] = r;
}

// ================= host-side drivers =================
static void build_csr(const int* src, const int* dst, int n,
                      int* row, int* cnt, int* ssrc, int* bsum) {
    int nb = (n + 1023) / 1024;
    zero_int<<<(n + 255) / 256, 256>>>(cnt, n);
    count_k<<<(NE + 255) / 256, 256>>>(dst, cnt, NE);
    scan_block<<<nb, 1024>>>(cnt, row, bsum, n);
    scan_bsum<<<1, 128>>>(bsum, nb);
    add_off<<<nb, 1024>>>(row, bsum, n);
    zero_int<<<(n + 255) / 256, 256>>>(cnt, n);
    scatter_k<<<(NE + 255) / 256, 256>>>(src, dst, row, cnt, ssrc, NE);
}

static void run_gat(const float* x_src, int Ns, int Fs,
                    const float* x_dst, int Nd, int Fd,
                    const int* row, const int* cnt, const int* ssrc,
                    const float* Ws, const float* Wd,
                    const float* a_s, const float* a_d, const float* b,
                    int H, int C, float* out, int do_relu,
                    float* hsbuf, float* hdbuf, float* SS, float* SD) {
    int D = H * C;
    dim3 g1((D + 127) / 128, (Ns + 127) / 128);
    gemm128<<<g1, 256>>>(x_src, Ws, hsbuf, Ns, D, Fs);
    dim3 g2((D + 127) / 128, (Nd + 127) / 128);
    gemm128<<<g2, 256>>>(x_dst, Wd, hdbuf, Nd, D, Fd);

    scores_kernel<<<(Ns * H * 32 + 255) / 256, 256>>>(hsbuf, a_s, SS, Ns, H, C);
    scores_kernel<<<(Nd * H * 32 + 255) / 256, 256>>>(hdbuf, a_d, SD, Nd, H, C);

    if (H == 8)
        gat_agg<8, 16><<<Nd, 128>>>(hsbuf, SS, SD, row, cnt, ssrc, b, out, do_relu);
    else
        gat_agg<4, 128><<<Nd, 128>>>(hsbuf, SS, SD, row, cnt, ssrc, b, out, do_relu);
}

extern "C" void kernel_launch(void* const* d_in, const int* in_sizes, int n_in,
                              void* d_out, int out_size) {
    const float* xu     = (const float*)d_in[0];
    const float* xm     = (const float*)d_in[1];
    const int*   um_src = (const int*)d_in[2];
    const int*   um_dst = (const int*)d_in[3];
    const int*   mu_src = (const int*)d_in[4];
    const int*   mu_dst = (const int*)d_in[5];
    const int*   lab_u  = (const int*)d_in[6];
    const int*   lab_m  = (const int*)d_in[7];
    const float* w1um_s = (const float*)d_in[8];
    const float* w1um_d = (const float*)d_in[9];
    const float* a1um_s = (const float*)d_in[10];
    const float* a1um_d = (const float*)d_in[11];
    const float* b1um   = (const float*)d_in[12];
    const float* w1mu_s = (const float*)d_in[13];
    const float* w1mu_d = (const float*)d_in[14];
    const float* a1mu_s = (const float*)d_in[15];
    const float* a1mu_d = (const float*)d_in[16];
    const float* b1mu   = (const float*)d_in[17];
    const float* w2um_s = (const float*)d_in[18];
    const float* w2um_d = (const float*)d_in[19];
    const float* a2um_s = (const float*)d_in[20];
    const float* a2um_d = (const float*)d_in[21];
    const float* b2um   = (const float*)d_in[22];
    const float* w2mu_s = (const float*)d_in[23];
    const float* w2mu_d = (const float*)d_in[24];
    const float* a2mu_s = (const float*)d_in[25];
    const float* a2mu_d = (const float*)d_in[26];
    const float* b2mu   = (const float*)d_in[27];
    const float* dw1    = (const float*)d_in[28];
    const float* db1    = (const float*)d_in[29];
    const float* dw2    = (const float*)d_in[30];
    const float* db2    = (const float*)d_in[31];

    float *BIG, *SMALL, *ZU1, *ZM1, *ZU2, *ZM2, *SS, *SD, *PREU, *PREM;
    int *ROW_UM, *CNT_UM, *SSRC_UM, *ROW_MU, *CNT_MU, *SSRC_MU, *BSUM;
    cudaGetSymbolAddress((void**)&BIG,     g_big);
    cudaGetSymbolAddress((void**)&SMALL,   g_small);
    cudaGetSymbolAddress((void**)&ZU1,     g_zu1);
    cudaGetSymbolAddress((void**)&ZM1,     g_zm1);
    cudaGetSymbolAddress((void**)&ZU2,     g_zu2);
    cudaGetSymbolAddress((void**)&ZM2,     g_zm2);
    cudaGetSymbolAddress((void**)&SS,      g_ss);
    cudaGetSymbolAddress((void**)&SD,      g_sd);
    cudaGetSymbolAddress((void**)&PREU,    g_preu);
    cudaGetSymbolAddress((void**)&PREM,    g_prem);
    cudaGetSymbolAddress((void**)&ROW_UM,  g_row_um);
    cudaGetSymbolAddress((void**)&CNT_UM,  g_cnt_um);
    cudaGetSymbolAddress((void**)&SSRC_UM, g_ssrc_um);
    cudaGetSymbolAddress((void**)&ROW_MU,  g_row_mu);
    cudaGetSymbolAddress((void**)&CNT_MU,  g_cnt_mu);
    cudaGetSymbolAddress((void**)&SSRC_MU, g_ssrc_mu);
    cudaGetSymbolAddress((void**)&BSUM,    g_bsum);

    // ---- CSR build (edge lists shared by both layers) ----
    build_csr(um_src, um_dst, NM, ROW_UM, CNT_UM, SSRC_UM, BSUM);
    build_csr(mu_src, mu_dst, NU, ROW_MU, CNT_MU, SSRC_MU, BSUM);

    // ---- layer 1 ----
    run_gat(xu, NU, FU, xm, NM, FM, ROW_UM, CNT_UM, SSRC_UM,
            w1um_s, w1um_d, a1um_s, a1um_d, b1um,
            H1, C1, ZM1, 1, BIG, SMALL, SS, SD);
    run_gat(xm, NM, FM, xu, NU, FU, ROW_MU, CNT_MU, SSRC_MU,
            w1mu_s, w1mu_d, a1mu_s, a1mu_d, b1mu,
            H1, C1, ZU1, 1, SMALL, BIG, SS, SD);

    // ---- layer 2 ----
    run_gat(ZU1, NU, D1, ZM1, NM, D1, ROW_UM, CNT_UM, SSRC_UM,
            w2um_s, w2um_d, a2um_s, a2um_d, b2um,
            H2, C2, ZM2, 0, BIG, SMALL, SS, SD);
    run_gat(ZM1, NM, D1, ZU1, NU, D1, ROW_MU, CNT_MU, SSRC_MU,
            w2mu_s, w2mu_d, a2mu_s, a2mu_d, b2mu,
            H2, C2, ZU2, 0, SMALL, BIG, SS, SD);

    // ---- edge decoder ----
    pre_kernel<<<(NU + 127) / 128, 128>>>(ZU2, dw1, PREU, NU, 0);
    pre_kernel<<<(NM + 127) / 128, 128>>>(ZM2, dw1, PREM, NM, 512);
    dec_final<<<(NEL + 255) / 256, 256>>>(PREU, PREM, lab_u, lab_m,
                                          db1, dw2, db2, (float*)d_out, NEL);
}

// round 3
// speedup vs baseline: 5.5682x; 1.3530x over previous
#include <cuda_runtime.h>
#include <math.h>

// ---------------- problem constants ----------------
#define NU 100000
#define NM 20000
#define FU 32
#define FM 128
#define H1 8
#define C1 16
#define D1 128   // H1*C1
#define H2 4
#define C2 128
#define D2 512   // H2*C2
#define NE 250000
#define NEL 200000

// ---------------- device scratch (no runtime alloc allowed) ----------------
__device__ float g_big  [(size_t)NU * D2];
__device__ float g_small[(size_t)NM * D2];
__device__ float g_zu1  [(size_t)NU * D1];
__device__ float g_zm1  [(size_t)NM * D1];
__device__ float g_zu2  [(size_t)NU * D2];
__device__ float g_zm2  [(size_t)NM * D2];
__device__ float g_ss   [NU * H1];
__device__ float g_sd   [NU * H1];
__device__ float g_preu [(size_t)NU * 16];
__device__ float g_prem [(size_t)NM * 16];
__device__ int g_row_um[NM];
__device__ int g_cnt_um[NM];
__device__ int g_ssrc_um[NE];
__device__ int g_row_mu[NU];
__device__ int g_cnt_mu[NU];
__device__ int g_ssrc_mu[NE];
__device__ int g_bsum[128];

// ---------------- helpers ----------------
__device__ __forceinline__ unsigned enc_f(float f) {
    unsigned u = __float_as_uint(f);
    return (u & 0x80000000u) ? ~u : (u | 0x80000000u);
}
__device__ __forceinline__ float dec_f(unsigned u) {
    return (u & 0x80000000u) ? __uint_as_float(u ^ 0x80000000u)
                             : __uint_as_float(~u);
}
__device__ __forceinline__ unsigned f2tf(float x) {
    unsigned u;
    asm("cvt.rna.tf32.f32 %0, %1;" : "=r"(u) : "f"(x));
    return u;
}

// ================= TF32 tensor-core GEMM =================
// C[M,N] = A[M,K] @ B[K,N]; N%128==0, K%16==0; M arbitrary.
// Block 128x128x16, 8 warps each 64x32, mma.m16n8k8.tf32.
#define TBM 128
#define TBN 128
#define TBK 16
#define TPAD 4

__global__ void __launch_bounds__(256, 2)
gemm_tf32(const float* __restrict__ A, const float* __restrict__ B,
          float* __restrict__ C, int M, int N, int K) {
    __shared__ unsigned As[TBK][TBM + TPAD];   // k-major
    __shared__ unsigned Bs[TBK][TBN + TPAD];   // k-major

    const int tid  = threadIdx.x;
    const int lane = tid & 31;
    const int wid  = tid >> 5;
    const int row0 = blockIdx.y * TBM;
    const int col0 = blockIdx.x * TBN;
    const int wm0  = (wid & 1) * 64;
    const int wn0  = (wid >> 1) * 32;
    const int lr   = lane >> 2;   // 0..7
    const int lc   = lane & 3;    // 0..3

    float acc[4][4][4];
#pragma unroll
    for (int mt = 0; mt < 4; mt++)
#pragma unroll
        for (int nt = 0; nt < 4; nt++)
#pragma unroll
            for (int q = 0; q < 4; q++) acc[mt][nt][q] = 0.f;

    const int nkt = K / TBK;
    for (int t = 0; t < nkt; t++) {
        const int k0 = t * TBK;
        // load A tile (transpose to k-major, tf32-round)
#pragma unroll
        for (int i = tid; i < TBM * (TBK / 4); i += 256) {
            int r = i >> 2, kq = (i & 3) * 4;
            int gr = row0 + r;
            float4 v = make_float4(0.f, 0.f, 0.f, 0.f);
            if (gr < M) v = *(const float4*)(A + (size_t)gr * K + k0 + kq);
            As[kq + 0][r] = f2tf(v.x);
            As[kq + 1][r] = f2tf(v.y);
            As[kq + 2][r] = f2tf(v.z);
            As[kq + 3][r] = f2tf(v.w);
        }
        // load B tile (already k-major, tf32-round)
#pragma unroll
        for (int i = tid; i < TBK * (TBN / 4); i += 256) {
            int k = i >> 5, cq = (i & 31) * 4;
            float4 v = *(const float4*)(B + (size_t)(k0 + k) * N + col0 + cq);
            Bs[k][cq + 0] = f2tf(v.x);
            Bs[k][cq + 1] = f2tf(v.y);
            Bs[k][cq + 2] = f2tf(v.z);
            Bs[k][cq + 3] = f2tf(v.w);
        }
        __syncthreads();

#pragma unroll
        for (int ks = 0; ks < TBK; ks += 8) {
            unsigned af[4][4], bf[4][2];
#pragma unroll
            for (int mt = 0; mt < 4; mt++) {
                int r = wm0 + mt * 16 + lr;
                int c = ks + lc;
                af[mt][0] = As[c][r];
                af[mt][1] = As[c][r + 8];
                af[mt][2] = As[c + 4][r];
                af[mt][3] = As[c + 4][r + 8];
            }
#pragma unroll
            for (int nt = 0; nt < 4; nt++) {
                int n = wn0 + nt * 8 + lr;
                int k = ks + lc;
                bf[nt][0] = Bs[k][n];
                bf[nt][1] = Bs[k + 4][n];
            }
#pragma unroll
            for (int mt = 0; mt < 4; mt++)
#pragma unroll
                for (int nt = 0; nt < 4; nt++) {
                    float* d = acc[mt][nt];
                    asm volatile(
                        "mma.sync.aligned.m16n8k8.row.col.f32.tf32.tf32.f32 "
                        "{%0,%1,%2,%3}, {%4,%5,%6,%7}, {%8,%9}, {%0,%1,%2,%3};\n"
                        : "+f"(d[0]), "+f"(d[1]), "+f"(d[2]), "+f"(d[3])
                        : "r"(af[mt][0]), "r"(af[mt][1]), "r"(af[mt][2]), "r"(af[mt][3]),
                          "r"(bf[nt][0]), "r"(bf[nt][1]));
                }
        }
        __syncthreads();
    }

    // store C: thread owns rows lr, lr+8; cols lc*2, lc*2+1 per 16x8 tile
#pragma unroll
    for (int mt = 0; mt < 4; mt++) {
#pragma unroll
        for (int half = 0; half < 2; half++) {
            int gr = row0 + wm0 + mt * 16 + lr + half * 8;
            if (gr < M) {
#pragma unroll
                for (int nt = 0; nt < 4; nt++) {
                    float2 v = half ? make_float2(acc[mt][nt][2], acc[mt][nt][3])
                                    : make_float2(acc[mt][nt][0], acc[mt][nt][1]);
                    *(float2*)(C + (size_t)gr * N + col0 + wn0 + nt * 8 + lc * 2) = v;
                }
            }
        }
    }
}

// ================= per-node attention score =================
__global__ void scores_kernel(const float* __restrict__ h, const float* __restrict__ a,
                              float* __restrict__ s, int N, int H, int C) {
    int warp = (blockIdx.x * blockDim.x + threadIdx.x) >> 5;
    int lane = threadIdx.x & 31;
    if (warp >= N * H) return;
    int n = warp / H, hh = warp % H;
    const float* hp = h + (size_t)n * H * C + hh * C;
    const float* ap = a + hh * C;
    float acc = 0.f;
    for (int c = lane; c < C; c += 32) acc += hp[c] * ap[c];
#pragma unroll
    for (int o = 16; o; o >>= 1) acc += __shfl_xor_sync(0xffffffffu, acc, o);
    if (lane == 0) s[warp] = acc;
}

// ================= CSR build kernels =================
__global__ void zero_int(int* __restrict__ p, int n) {
    int i = blockIdx.x * blockDim.x + threadIdx.x;
    if (i < n) p[i] = 0;
}
__global__ void count_k(const int* __restrict__ dst, int* __restrict__ cnt, int E) {
    int i = blockIdx.x * blockDim.x + threadIdx.x;
    if (i < E) atomicAdd(&cnt[dst[i]], 1);
}
__global__ void scan_block(const int* __restrict__ cnt, int* __restrict__ row,
                           int* __restrict__ bsum, int n) {
    __shared__ int sh[1024];
    int i = blockIdx.x * 1024 + threadIdx.x;
    int v = (i < n) ? cnt[i] : 0;
    sh[threadIdx.x] = v;
    __syncthreads();
    for (int o = 1; o < 1024; o <<= 1) {
        int t = (threadIdx.x >= o) ? sh[threadIdx.x - o] : 0;
        __syncthreads();
        sh[threadIdx.x] += t;
        __syncthreads();
    }
    if (i < n) row[i] = sh[threadIdx.x] - v;
    if (threadIdx.x == 1023) bsum[blockIdx.x] = sh[1023];
}
__global__ void scan_bsum(int* __restrict__ bsum, int nb) {
    __shared__ int sh[128];
    int t = threadIdx.x;
    int v = (t < nb) ? bsum[t] : 0;
    sh[t] = v;
    __syncthreads();
    for (int o = 1; o < 128; o <<= 1) {
        int x = (t >= o) ? sh[t - o] : 0;
        __syncthreads();
        sh[t] += x;
        __syncthreads();
    }
    if (t < nb) bsum[t] = sh[t] - v;
}
__global__ void add_off(int* __restrict__ row, const int* __restrict__ bsum, int n) {
    int i = blockIdx.x * 1024 + threadIdx.x;
    if (i < n) row[i] += bsum[blockIdx.x];
}
__global__ void scatter_k(const int* __restrict__ src, const int* __restrict__ dst,
                          const int* __restrict__ row, int* __restrict__ cur,
                          int* __restrict__ ssrc, int E) {
    int e = blockIdx.x * blockDim.x + threadIdx.x;
    if (e >= E) return;
    int d = dst[e];
    int pos = row[d] + atomicAdd(&cur[d], 1);
    ssrc[pos] = src[e];
}

// ================= fused softmax + aggregate + finalize (block per dst) =================
template <int H, int C>
__global__ void __launch_bounds__(128)
gat_agg(const float* __restrict__ hs, const float* __restrict__ ss,
        const float* __restrict__ sd, const int* __restrict__ row,
        const int* __restrict__ deg_, const int* __restrict__ ssrc,
        const float* __restrict__ b, float* __restrict__ out, int do_relu) {
    constexpr int D = H * C;
    constexpr int PC = D / 128;
    constexpr int CAP = 2048 / H;
    const int d = blockIdx.x;
    const int tid = threadIdx.x;
    const int start = row[d];
    const int deg = deg_[d];

    __shared__ unsigned smax[H];
    __shared__ float ssum[H];
    __shared__ float sdd[H];
    __shared__ float sal[2048];

    if (tid < H) { smax[tid] = 0u; ssum[tid] = 0.f; sdd[tid] = sd[d * H + tid]; }
    __syncthreads();

    for (int i = tid; i < deg * H; i += 128) {
        int k = i / H, h = i - k * H;
        int s = ssrc[start + k];
        float v = ss[s * H + h] + sdd[h];
        v = (v > 0.f) ? v : 0.2f * v;
        atomicMax(&smax[h], enc_f(v));
    }
    __syncthreads();
    for (int i = tid; i < deg * H; i += 128) {
        int k = i / H, h = i - k * H;
        int s = ssrc[start + k];
        float v = ss[s * H + h] + sdd[h];
        v = (v > 0.f) ? v : 0.2f * v;
        float ex = __expf(v - dec_f(smax[h]));
        if (k < CAP) sal[k * H + h] = ex;
        atomicAdd(&ssum[h], ex);
    }
    __syncthreads();
    float acc[PC];
#pragma unroll
    for (int j = 0; j < PC; j++) acc[j] = 0.f;
    for (int k = 0; k < deg; k++) {
        int s = ssrc[start + k];
        const float* hp = hs + (size_t)s * D;
#pragma unroll
        for (int j = 0; j < PC; j++) {
            int ch = tid + j * 128;
            int h = ch / C;
            float w;
            if (k < CAP) {
                w = sal[k * H + h];
            } else {
                float v = ss[s * H + h] + sdd[h];
                v = (v > 0.f) ? v : 0.2f * v;
                w = __expf(v - dec_f(smax[h]));
            }
            acc[j] += w * hp[ch];
        }
    }
#pragma unroll
    for (int j = 0; j < PC; j++) {
        int ch = tid + j * 128;
        int h = ch / C;
        float v = acc[j] / (ssum[h] + 1e-16f) + b[ch];
        if (do_relu) v = fmaxf(v, 0.f);
        out[(size_t)d * D + ch] = v;
    }
}

// ================= decoder =================
__global__ void __launch_bounds__(128)
pre_kernel(const float* __restrict__ z, const float* __restrict__ dw1,
           float* __restrict__ pre, int N, int roff) {
    __shared__ float sw[512 * 16];
    const int tid = threadIdx.x;
    for (int i = tid; i < 512 * 16; i += 128) sw[i] = dw1[(size_t)roff * 16 + i];
    __syncthreads();
    int n = blockIdx.x * 128 + tid;
    if (n >= N) return;
    const float4* zp = (const float4*)(z + (size_t)n * 512);
    float acc[16];
#pragma unroll
    for (int j = 0; j < 16; j++) acc[j] = 0.f;
    for (int kq = 0; kq < 128; kq++) {
        float4 zv = zp[kq];
        const float* w0 = &sw[(kq * 4 + 0) * 16];
        const float* w1 = &sw[(kq * 4 + 1) * 16];
        const float* w2 = &sw[(kq * 4 + 2) * 16];
        const float* w3 = &sw[(kq * 4 + 3) * 16];
#pragma unroll
        for (int j = 0; j < 16; j++)
            acc[j] += zv.x * w0[j] + zv.y * w1[j] + zv.z * w2[j] + zv.w * w3[j];
    }
#pragma unroll
    for (int j = 0; j < 16; j++) pre[(size_t)n * 16 + j] = acc[j];
}

__global__ void dec_final(const float* __restrict__ preu, const float* __restrict__ prem,
                          const int* __restrict__ lu, const int* __restrict__ lm,
                          const float* __restrict__ db1, const float* __restrict__ dw2,
                          const float* __restrict__ db2, float* __restrict__ out, int EL) {
    int i = blockIdx.x * blockDim.x + threadIdx.x;
    if (i >= EL) return;
    const float* pu = preu + (size_t)lu[i] * 16;
    const float* pm = prem + (size_t)lm[i] * 16;
    float r = db2[0];
#pragma unroll
    for (int j = 0; j < 16; j++) {
        float h = fmaxf(pu[j] + pm[j] + db1[j], 0.f);
        r += h * dw2[j];
    }
    out[i] = r;
}

// ================= host-side drivers =================
static void build_csr(const int* src, const int* dst, int n,
                      int* row, int* cnt, int* ssrc, int* bsum) {
    int nb = (n + 1023) / 1024;
    zero_int<<<(n + 255) / 256, 256>>>(cnt, n);
    count_k<<<(NE + 255) / 256, 256>>>(dst, cnt, NE);
    scan_block<<<nb, 1024>>>(cnt, row, bsum, n);
    scan_bsum<<<1, 128>>>(bsum, nb);
    add_off<<<nb, 1024>>>(row, bsum, n);
    zero_int<<<(n + 255) / 256, 256>>>(cnt, n);
    scatter_k<<<(NE + 255) / 256, 256>>>(src, dst, row, cnt, ssrc, NE);
}

static void run_gat(const float* x_src, int Ns, int Fs,
                    const float* x_dst, int Nd, int Fd,
                    const int* row, const int* cnt, const int* ssrc,
                    const float* Ws, const float* Wd,
                    const float* a_s, const float* a_d, const float* b,
                    int H, int C, float* out, int do_relu,
                    float* hsbuf, float* hdbuf, float* SS, float* SD) {
    int D = H * C;
    dim3 g1(D / TBN, (Ns + TBM - 1) / TBM);
    gemm_tf32<<<g1, 256>>>(x_src, Ws, hsbuf, Ns, D, Fs);
    dim3 g2(D / TBN, (Nd + TBM - 1) / TBM);
    gemm_tf32<<<g2, 256>>>(x_dst, Wd, hdbuf, Nd, D, Fd);

    scores_kernel<<<(Ns * H * 32 + 255) / 256, 256>>>(hsbuf, a_s, SS, Ns, H, C);
    scores_kernel<<<(Nd * H * 32 + 255) / 256, 256>>>(hdbuf, a_d, SD, Nd, H, C);

    if (H == 8)
        gat_agg<8, 16><<<Nd, 128>>>(hsbuf, SS, SD, row, cnt, ssrc, b, out, do_relu);
    else
        gat_agg<4, 128><<<Nd, 128>>>(hsbuf, SS, SD, row, cnt, ssrc, b, out, do_relu);
}

extern "C" void kernel_launch(void* const* d_in, const int* in_sizes, int n_in,
                              void* d_out, int out_size) {
    const float* xu     = (const float*)d_in[0];
    const float* xm     = (const float*)d_in[1];
    const int*   um_src = (const int*)d_in[2];
    const int*   um_dst = (const int*)d_in[3];
    const int*   mu_src = (const int*)d_in[4];
    const int*   mu_dst = (const int*)d_in[5];
    const int*   lab_u  = (const int*)d_in[6];
    const int*   lab_m  = (const int*)d_in[7];
    const float* w1um_s = (const float*)d_in[8];
    const float* w1um_d = (const float*)d_in[9];
    const float* a1um_s = (const float*)d_in[10];
    const float* a1um_d = (const float*)d_in[11];
    const float* b1um   = (const float*)d_in[12];
    const float* w1mu_s = (const float*)d_in[13];
    const float* w1mu_d = (const float*)d_in[14];
    const float* a1mu_s = (const float*)d_in[15];
    const float* a1mu_d = (const float*)d_in[16];
    const float* b1mu   = (const float*)d_in[17];
    const float* w2um_s = (const float*)d_in[18];
    const float* w2um_d = (const float*)d_in[19];
    const float* a2um_s = (const float*)d_in[20];
    const float* a2um_d = (const float*)d_in[21];
    const float* b2um   = (const float*)d_in[22];
    const float* w2mu_s = (const float*)d_in[23];
    const float* w2mu_d = (const float*)d_in[24];
    const float* a2mu_s = (const float*)d_in[25];
    const float* a2mu_d = (const float*)d_in[26];
    const float* b2mu   = (const float*)d_in[27];
    const float* dw1    = (const float*)d_in[28];
    const float* db1    = (const float*)d_in[29];
    const float* dw2    = (const float*)d_in[30];
    const float* db2    = (const float*)d_in[31];

    float *BIG, *SMALL, *ZU1, *ZM1, *ZU2, *ZM2, *SS, *SD, *PREU, *PREM;
    int *ROW_UM, *CNT_UM, *SSRC_UM, *ROW_MU, *CNT_MU, *SSRC_MU, *BSUM;
    cudaGetSymbolAddress((void**)&BIG,     g_big);
    cudaGetSymbolAddress((void**)&SMALL,   g_small);
    cudaGetSymbolAddress((void**)&ZU1,     g_zu1);
    cudaGetSymbolAddress((void**)&ZM1,     g_zm1);
    cudaGetSymbolAddress((void**)&ZU2,     g_zu2);
    cudaGetSymbolAddress((void**)&ZM2,     g_zm2);
    cudaGetSymbolAddress((void**)&SS,      g_ss);
    cudaGetSymbolAddress((void**)&SD,      g_sd);
    cudaGetSymbolAddress((void**)&PREU,    g_preu);
    cudaGetSymbolAddress((void**)&PREM,    g_prem);
    cudaGetSymbolAddress((void**)&ROW_UM,  g_row_um);
    cudaGetSymbolAddress((void**)&CNT_UM,  g_cnt_um);
    cudaGetSymbolAddress((void**)&SSRC_UM, g_ssrc_um);
    cudaGetSymbolAddress((void**)&ROW_MU,  g_row_mu);
    cudaGetSymbolAddress((void**)&CNT_MU,  g_cnt_mu);
    cudaGetSymbolAddress((void**)&SSRC_MU, g_ssrc_mu);
    cudaGetSymbolAddress((void**)&BSUM,    g_bsum);

    build_csr(um_src, um_dst, NM, ROW_UM, CNT_UM, SSRC_UM, BSUM);
    build_csr(mu_src, mu_dst, NU, ROW_MU, CNT_MU, SSRC_MU, BSUM);

    run_gat(xu, NU, FU, xm, NM, FM, ROW_UM, CNT_UM, SSRC_UM,
            w1um_s, w1um_d, a1um_s, a1um_d, b1um,
            H1, C1, ZM1, 1, BIG, SMALL, SS, SD);
    run_gat(xm, NM, FM, xu, NU, FU, ROW_MU, CNT_MU, SSRC_MU,
            w1mu_s, w1mu_d, a1mu_s, a1mu_d, b1mu,
            H1, C1, ZU1, 1, SMALL, BIG, SS, SD);

    run_gat(ZU1, NU, D1, ZM1, NM, D1, ROW_UM, CNT_UM, SSRC_UM,
            w2um_s, w2um_d, a2um_s, a2um_d, b2um,
            H2, C2, ZM2, 0, BIG, SMALL, SS, SD);
    run_gat(ZM1, NM, D1, ZU1, NU, D1, ROW_MU, CNT_MU, SSRC_MU,
            w2mu_s, w2mu_d, a2mu_s, a2mu_d, b2mu,
            H2, C2, ZU2, 0, SMALL, BIG, SS, SD);

    pre_kernel<<<(NU + 127) / 128, 128>>>(ZU2, dw1, PREU, NU, 0);
    pre_kernel<<<(NM + 127) / 128, 128>>>(ZM2, dw1, PREM, NM, 512);
    dec_final<<<(NEL + 255) / 256, 256>>>(PREU, PREM, lab_u, lab_m,
                                          db1, dw2, db2, (float*)d_out, NEL);
}

// round 4
// speedup vs baseline: 6.9402x; 1.2464x over previous
#include <cuda_runtime.h>
#include <math.h>

// ---------------- problem constants ----------------
#define NU 100000
#define NM 20000
#define FU 32
#define FM 128
#define H1 8
#define C1 16
#define D1 128   // H1*C1
#define H2 4
#define C2 128
#define D2 512   // H2*C2
#define NE 250000
#define NEL 200000
#define NTOT (NM + NU)   // combined CSR buckets: um dsts [0,NM), mu dsts [NM,NTOT)

// ---------------- device scratch (no runtime alloc allowed) ----------------
__device__ float g_big  [(size_t)NU * D2];
__device__ float g_small[(size_t)NM * D2];
__device__ float g_zu1  [(size_t)NU * D1];
__device__ float g_zm1  [(size_t)NM * D1];
__device__ float g_zu2  [(size_t)NU * D2];
__device__ float g_zm2  [(size_t)NM * D2];
__device__ float g_ss   [NU * H1];
__device__ float g_sd   [NU * H1];
__device__ float g_preu [(size_t)NU * 16];
__device__ float g_prem [(size_t)NM * 16];
__device__ int g_row [NTOT];
__device__ int g_cur [NTOT];
__device__ int g_ssrc[2 * NE];
__device__ int g_bsum[128];

// ---------------- helpers ----------------
__device__ __forceinline__ unsigned enc_f(float f) {
    unsigned u = __float_as_uint(f);
    return (u & 0x80000000u) ? ~u : (u | 0x80000000u);
}
__device__ __forceinline__ float dec_f(unsigned u) {
    return (u & 0x80000000u) ? __uint_as_float(u ^ 0x80000000u)
                             : __uint_as_float(~u);
}
__device__ __forceinline__ unsigned f2tf(float x) {
    unsigned u;
    asm("cvt.rna.tf32.f32 %0, %1;" : "=r"(u) : "f"(x));
    return u;
}

// ================= TF32 tensor-core GEMM w/ fused attention-score epilogue ===========
// C[M,N] = A[M,K] @ B[K,N]; N%128==0, K%16==0; M arbitrary.
// If sout != nullptr: also s[n,h] = sum_c C[n, h*Cd+c] * avec[h*Cd+c].
// Requires each head's Cd columns fully inside one 128-col block (true for D1/D2 here).
#define TBM 128
#define TBN 128
#define TBK 16
#define TPAD 4

__global__ void __launch_bounds__(256, 2)
gemm_tf32(const float* __restrict__ A, const float* __restrict__ B,
          float* __restrict__ C, int M, int N, int K,
          const float* __restrict__ avec, float* __restrict__ sout,
          int Cd, int Htot) {
    __shared__ unsigned As[2][TBK][TBM + TPAD];   // k-major
    __shared__ unsigned Bs[2][TBK][TBN + TPAD];   // k-major
    __shared__ float sred[TBM][8];

    const int tid  = threadIdx.x;
    const int lane = tid & 31;
    const int wid  = tid >> 5;
    const int row0 = blockIdx.y * TBM;
    const int col0 = blockIdx.x * TBN;
    const int wm0  = (wid & 1) * 64;
    const int wn0  = (wid >> 1) * 32;
    const int lr   = lane >> 2;   // 0..7
    const int lc   = lane & 3;    // 0..3

    float acc[4][4][4];
#pragma unroll
    for (int mt = 0; mt < 4; mt++)
#pragma unroll
        for (int nt = 0; nt < 4; nt++)
#pragma unroll
            for (int q = 0; q < 4; q++) acc[mt][nt][q] = 0.f;

    // loader indices (2 float4 each for A and B per thread)
    float4 aR[2], bR[2];
    const int nkt = K / TBK;

    // prologue: tile 0 -> regs -> smem[0]
#pragma unroll
    for (int it = 0; it < 2; it++) {
        int idx = tid + it * 256;
        int r = idx >> 2, kq = (idx & 3) * 4;
        int gr = row0 + r;
        aR[it] = make_float4(0.f, 0.f, 0.f, 0.f);
        if (gr < M) aR[it] = *(const float4*)(A + (size_t)gr * K + kq);
        int k = idx >> 5, cq = (idx & 31) * 4;
        bR[it] = *(const float4*)(B + (size_t)k * N + col0 + cq);
    }
#pragma unroll
    for (int it = 0; it < 2; it++) {
        int idx = tid + it * 256;
        int r = idx >> 2, kq = (idx & 3) * 4;
        As[0][kq + 0][r] = f2tf(aR[it].x);
        As[0][kq + 1][r] = f2tf(aR[it].y);
        As[0][kq + 2][r] = f2tf(aR[it].z);
        As[0][kq + 3][r] = f2tf(aR[it].w);
        int k = idx >> 5, cq = (idx & 31) * 4;
        Bs[0][k][cq + 0] = f2tf(bR[it].x);
        Bs[0][k][cq + 1] = f2tf(bR[it].y);
        Bs[0][k][cq + 2] = f2tf(bR[it].z);
        Bs[0][k][cq + 3] = f2tf(bR[it].w);
    }
    __syncthreads();

    for (int t = 0; t < nkt; t++) {
        // prefetch next tile to regs (overlaps with compute below)
        if (t + 1 < nkt) {
            int k0 = (t + 1) * TBK;
#pragma unroll
            for (int it = 0; it < 2; it++) {
                int idx = tid + it * 256;
                int r = idx >> 2, kq = (idx & 3) * 4;
                int gr = row0 + r;
                aR[it] = make_float4(0.f, 0.f, 0.f, 0.f);
                if (gr < M) aR[it] = *(const float4*)(A + (size_t)gr * K + k0 + kq);
                int k = idx >> 5, cq = (idx & 31) * 4;
                bR[it] = *(const float4*)(B + (size_t)(k0 + k) * N + col0 + cq);
            }
        }
        const int buf = t & 1;
#pragma unroll
        for (int ks = 0; ks < TBK; ks += 8) {
            unsigned af[4][4], bf[4][2];
#pragma unroll
            for (int mt = 0; mt < 4; mt++) {
                int r = wm0 + mt * 16 + lr;
                int c = ks + lc;
                af[mt][0] = As[buf][c][r];
                af[mt][1] = As[buf][c][r + 8];
                af[mt][2] = As[buf][c + 4][r];
                af[mt][3] = As[buf][c + 4][r + 8];
            }
#pragma unroll
            for (int nt = 0; nt < 4; nt++) {
                int n = wn0 + nt * 8 + lr;
                int k = ks + lc;
                bf[nt][0] = Bs[buf][k][n];
                bf[nt][1] = Bs[buf][k + 4][n];
            }
#pragma unroll
            for (int mt = 0; mt < 4; mt++)
#pragma unroll
                for (int nt = 0; nt < 4; nt++) {
                    float* d = acc[mt][nt];
                    asm volatile(
                        "mma.sync.aligned.m16n8k8.row.col.f32.tf32.tf32.f32 "
                        "{%0,%1,%2,%3}, {%4,%5,%6,%7}, {%8,%9}, {%0,%1,%2,%3};\n"
                        : "+f"(d[0]), "+f"(d[1]), "+f"(d[2]), "+f"(d[3])
                        : "r"(af[mt][0]), "r"(af[mt][1]), "r"(af[mt][2]), "r"(af[mt][3]),
                          "r"(bf[nt][0]), "r"(bf[nt][1]));
                }
        }
        // stage next tile into the other buffer (safe: it was last read at t-1,
        // whose trailing __syncthreads already drained all readers)
        if (t + 1 < nkt) {
            const int nb = buf ^ 1;
#pragma unroll
            for (int it = 0; it < 2; it++) {
                int idx = tid + it * 256;
                int r = idx >> 2, kq = (idx & 3) * 4;
                As[nb][kq + 0][r] = f2tf(aR[it].x);
                As[nb][kq + 1][r] = f2tf(aR[it].y);
                As[nb][kq + 2][r] = f2tf(aR[it].z);
                As[nb][kq + 3][r] = f2tf(aR[it].w);
                int k = idx >> 5, cq = (idx & 31) * 4;
                Bs[nb][k][cq + 0] = f2tf(bR[it].x);
                Bs[nb][k][cq + 1] = f2tf(bR[it].y);
                Bs[nb][k][cq + 2] = f2tf(bR[it].z);
                Bs[nb][k][cq + 3] = f2tf(bR[it].w);
            }
            __syncthreads();
        }
    }

    // store C
#pragma unroll
    for (int mt = 0; mt < 4; mt++) {
#pragma unroll
        for (int half = 0; half < 2; half++) {
            int gr = row0 + wm0 + mt * 16 + lr + half * 8;
            if (gr < M) {
#pragma unroll
                for (int nt = 0; nt < 4; nt++) {
                    float2 v = half ? make_float2(acc[mt][nt][2], acc[mt][nt][3])
                                    : make_float2(acc[mt][nt][0], acc[mt][nt][1]);
                    *(float2*)(C + (size_t)gr * N + col0 + wn0 + nt * 8 + lc * 2) = v;
                }
            }
        }
    }

    // ---- fused score epilogue ----
    if (sout) {
        for (int i = tid; i < TBM * 8; i += 256) ((float*)sred)[i] = 0.f;
        __syncthreads();
        // per-thread a-vector values for its 8 columns
        float av0[4], av1[4];
        int grp[4];
        const int hl0 = wn0 / Cd;
        int hb = TBN / Cd; if (hb < 1) hb = 1; if (hb > 8) hb = 8;
#pragma unroll
        for (int nt = 0; nt < 4; nt++) {
            int gc = col0 + wn0 + nt * 8 + lc * 2;
            av0[nt] = __ldg(&avec[gc]);
            av1[nt] = __ldg(&avec[gc + 1]);
            grp[nt] = (wn0 + nt * 8) / Cd - hl0;   // 0 or 1
        }
#pragma unroll
        for (int mt = 0; mt < 4; mt++) {
#pragma unroll
            for (int half = 0; half < 2; half++) {
                float p0 = 0.f, p1 = 0.f;
#pragma unroll
                for (int nt = 0; nt < 4; nt++) {
                    float v = acc[mt][nt][half * 2] * av0[nt]
                            + acc[mt][nt][half * 2 + 1] * av1[nt];
                    if (grp[nt]) p1 += v; else p0 += v;
                }
                p0 += __shfl_xor_sync(0xffffffffu, p0, 1);
                p0 += __shfl_xor_sync(0xffffffffu, p0, 2);
                p1 += __shfl_xor_sync(0xffffffffu, p1, 1);
                p1 += __shfl_xor_sync(0xffffffffu, p1, 2);
                if (lc == 0) {
                    int r = wm0 + mt * 16 + lr + half * 8;
                    atomicAdd(&sred[r][hl0], p0);
                    if (hb > 1) atomicAdd(&sred[r][hl0 + 1], p1);
                }
            }
        }
        __syncthreads();
        const int hg0 = col0 / Cd;
        for (int i = tid; i < TBM * hb; i += 256) {
            int r = i / hb, hl = i - r * hb;
            int gr = row0 + r;
            if (gr < M) sout[(size_t)gr * Htot + hg0 + hl] = sred[r][hl];
        }
    }
}

// ================= combined CSR build kernels =================
__global__ void zero_int(int* __restrict__ p, int n) {
    int i = blockIdx.x * blockDim.x + threadIdx.x;
    if (i < n) p[i] = 0;
}
__global__ void count2_k(const int* __restrict__ um_dst, const int* __restrict__ mu_dst,
                         int* __restrict__ cnt) {
    int i = blockIdx.x * blockDim.x + threadIdx.x;
    if (i >= 2 * NE) return;
    int d = (i < NE) ? um_dst[i] : (NM + mu_dst[i - NE]);
    atomicAdd(&cnt[d], 1);
}
__global__ void scan_block(const int* __restrict__ cnt, int* __restrict__ row,
                           int* __restrict__ bsum, int n) {
    __shared__ int sh[1024];
    int i = blockIdx.x * 1024 + threadIdx.x;
    int v = (i < n) ? cnt[i] : 0;
    sh[threadIdx.x] = v;
    __syncthreads();
    for (int o = 1; o < 1024; o <<= 1) {
        int t = (threadIdx.x >= o) ? sh[threadIdx.x - o] : 0;
        __syncthreads();
        sh[threadIdx.x] += t;
        __syncthreads();
    }
    if (i < n) row[i] = sh[threadIdx.x] - v;
    if (threadIdx.x == 1023) bsum[blockIdx.x] = sh[1023];
}
__global__ void scan_bsum(int* __restrict__ bsum, int nb) {
    __shared__ int sh[128];
    int t = threadIdx.x;
    int v = (t < nb) ? bsum[t] : 0;
    sh[t] = v;
    __syncthreads();
    for (int o = 1; o < 128; o <<= 1) {
        int x = (t >= o) ? sh[t - o] : 0;
        __syncthreads();
        sh[t] += x;
        __syncthreads();
    }
    if (t < nb) bsum[t] = sh[t] - v;
}
__global__ void add_off(int* __restrict__ row, const int* __restrict__ bsum, int n) {
    int i = blockIdx.x * 1024 + threadIdx.x;
    if (i < n) row[i] += bsum[blockIdx.x];
}
__global__ void scatter2_k(const int* __restrict__ um_src, const int* __restrict__ um_dst,
                           const int* __restrict__ mu_src, const int* __restrict__ mu_dst,
                           const int* __restrict__ row, int* __restrict__ cur,
                           int* __restrict__ ssrc) {
    int i = blockIdx.x * blockDim.x + threadIdx.x;
    if (i >= 2 * NE) return;
    int d, s;
    if (i < NE) { d = um_dst[i]; s = um_src[i]; }
    else        { d = NM + mu_dst[i - NE]; s = mu_src[i - NE]; }
    int pos = row[d] + atomicAdd(&cur[d], 1);
    ssrc[pos] = s;
}

// ================= fused softmax + aggregate + finalize (block per dst) =================
template <int H, int C>
__global__ void __launch_bounds__(128)
gat_agg(const float* __restrict__ hs, const float* __restrict__ ss,
        const float* __restrict__ sd, const int* __restrict__ row,
        const int* __restrict__ deg_, const int* __restrict__ ssrc,
        const float* __restrict__ b, float* __restrict__ out, int do_relu) {
    constexpr int D = H * C;
    constexpr int PC = D / 128;
    constexpr int CAP = 2048 / H;
    const int d = blockIdx.x;
    const int tid = threadIdx.x;
    const int start = row[d];
    const int deg = deg_[d];

    __shared__ unsigned smax[H];
    __shared__ float ssum[H];
    __shared__ float sdd[H];
    __shared__ float sal[2048];

    if (tid < H) { smax[tid] = 0u; ssum[tid] = 0.f; sdd[tid] = sd[d * H + tid]; }
    __syncthreads();

    for (int i = tid; i < deg * H; i += 128) {
        int k = i / H, h = i - k * H;
        int s = ssrc[start + k];
        float v = ss[s * H + h] + sdd[h];
        v = (v > 0.f) ? v : 0.2f * v;
        atomicMax(&smax[h], enc_f(v));
    }
    __syncthreads();
    for (int i = tid; i < deg * H; i += 128) {
        int k = i / H, h = i - k * H;
        int s = ssrc[start + k];
        float v = ss[s * H + h] + sdd[h];
        v = (v > 0.f) ? v : 0.2f * v;
        float ex = __expf(v - dec_f(smax[h]));
        if (k < CAP) sal[k * H + h] = ex;
        atomicAdd(&ssum[h], ex);
    }
    __syncthreads();
    float acc[PC];
#pragma unroll
    for (int j = 0; j < PC; j++) acc[j] = 0.f;
    for (int k = 0; k < deg; k++) {
        int s = ssrc[start + k];
        const float* hp = hs + (size_t)s * D;
#pragma unroll
        for (int j = 0; j < PC; j++) {
            int ch = tid + j * 128;
            int h = ch / C;
            float w;
            if (k < CAP) {
                w = sal[k * H + h];
            } else {
                float v = ss[s * H + h] + sdd[h];
                v = (v > 0.f) ? v : 0.2f * v;
                w = __expf(v - dec_f(smax[h]));
            }
            acc[j] += w * hp[ch];
        }
    }
#pragma unroll
    for (int j = 0; j < PC; j++) {
        int ch = tid + j * 128;
        int h = ch / C;
        float v = acc[j] / (ssum[h] + 1e-16f) + b[ch];
        if (do_relu) v = fmaxf(v, 0.f);
        out[(size_t)d * D + ch] = v;
    }
}

// ================= decoder =================
__global__ void __launch_bounds__(128)
pre_kernel(const float* __restrict__ z, const float* __restrict__ dw1,
           float* __restrict__ pre, int N, int roff) {
    __shared__ float sw[512 * 16];
    const int tid = threadIdx.x;
    for (int i = tid; i < 512 * 16; i += 128) sw[i] = dw1[(size_t)roff * 16 + i];
    __syncthreads();
    int n = blockIdx.x * 128 + tid;
    if (n >= N) return;
    const float4* zp = (const float4*)(z + (size_t)n * 512);
    float acc[16];
#pragma unroll
    for (int j = 0; j < 16; j++) acc[j] = 0.f;
    for (int kq = 0; kq < 128; kq++) {
        float4 zv = zp[kq];
        const float* w0 = &sw[(kq * 4 + 0) * 16];
        const float* w1 = &sw[(kq * 4 + 1) * 16];
        const float* w2 = &sw[(kq * 4 + 2) * 16];
        const float* w3 = &sw[(kq * 4 + 3) * 16];
#pragma unroll
        for (int j = 0; j < 16; j++)
            acc[j] += zv.x * w0[j] + zv.y * w1[j] + zv.z * w2[j] + zv.w * w3[j];
    }
#pragma unroll
    for (int j = 0; j < 16; j++) pre[(size_t)n * 16 + j] = acc[j];
}

__global__ void dec_final(const float* __restrict__ preu, const float* __restrict__ prem,
                          const int* __restrict__ lu, const int* __restrict__ lm,
                          const float* __restrict__ db1, const float* __restrict__ dw2,
                          const float* __restrict__ db2, float* __restrict__ out, int EL) {
    int i = blockIdx.x * blockDim.x + threadIdx.x;
    if (i >= EL) return;
    const float* pu = preu + (size_t)lu[i] * 16;
    const float* pm = prem + (size_t)lm[i] * 16;
    float r = db2[0];
#pragma unroll
    for (int j = 0; j < 16; j++) {
        float h = fmaxf(pu[j] + pm[j] + db1[j], 0.f);
        r += h * dw2[j];
    }
    out[i] = r;
}

// ================= host-side drivers =================
static void run_gat(const float* x_src, int Ns, int Fs,
                    const float* x_dst, int Nd, int Fd,
                    const int* row, const int* deg, const int* ssrc,
                    const float* Ws, const float* Wd,
                    const float* a_s, const float* a_d, const float* b,
                    int H, int C, float* out, int do_relu,
                    float* hsbuf, float* hdbuf, float* SS, float* SD) {
    int D = H * C;
    dim3 g1(D / TBN, (Ns + TBM - 1) / TBM);
    gemm_tf32<<<g1, 256>>>(x_src, Ws, hsbuf, Ns, D, Fs, a_s, SS, C, H);
    dim3 g2(D / TBN, (Nd + TBM - 1) / TBM);
    gemm_tf32<<<g2, 256>>>(x_dst, Wd, hdbuf, Nd, D, Fd, a_d, SD, C, H);

    if (H == 8)
        gat_agg<8, 16><<<Nd, 128>>>(hsbuf, SS, SD, row, deg, ssrc, b, out, do_relu);
    else
        gat_agg<4, 128><<<Nd, 128>>>(hsbuf, SS, SD, row, deg, ssrc, b, out, do_relu);
}

extern "C" void kernel_launch(void* const* d_in, const int* in_sizes, int n_in,
                              void* d_out, int out_size) {
    const float* xu     = (const float*)d_in[0];
    const float* xm     = (const float*)d_in[1];
    const int*   um_src = (const int*)d_in[2];
    const int*   um_dst = (const int*)d_in[3];
    const int*   mu_src = (const int*)d_in[4];
    const int*   mu_dst = (const int*)d_in[5];
    const int*   lab_u  = (const int*)d_in[6];
    const int*   lab_m  = (const int*)d_in[7];
    const float* w1um_s = (const float*)d_in[8];
    const float* w1um_d = (const float*)d_in[9];
    const float* a1um_s = (const float*)d_in[10];
    const float* a1um_d = (const float*)d_in[11];
    const float* b1um   = (const float*)d_in[12];
    const float* w1mu_s = (const float*)d_in[13];
    const float* w1mu_d = (const float*)d_in[14];
    const float* a1mu_s = (const float*)d_in[15];
    const float* a1mu_d = (const float*)d_in[16];
    const float* b1mu   = (const float*)d_in[17];
    const float* w2um_s = (const float*)d_in[18];
    const float* w2um_d = (const float*)d_in[19];
    const float* a2um_s = (const float*)d_in[20];
    const float* a2um_d = (const float*)d_in[21];
    const float* b2um   = (const float*)d_in[22];
    const float* w2mu_s = (const float*)d_in[23];
    const float* w2mu_d = (const float*)d_in[24];
    const float* a2mu_s = (const float*)d_in[25];
    const float* a2mu_d = (const float*)d_in[26];
    const float* b2mu   = (const float*)d_in[27];
    const float* dw1    = (const float*)d_in[28];
    const float* db1    = (const float*)d_in[29];
    const float* dw2    = (const float*)d_in[30];
    const float* db2    = (const float*)d_in[31];

    float *BIG, *SMALL, *ZU1, *ZM1, *ZU2, *ZM2, *SS, *SD, *PREU, *PREM;
    int *ROW, *CUR, *SSRC, *BSUM;
    cudaGetSymbolAddress((void**)&BIG,   g_big);
    cudaGetSymbolAddress((void**)&SMALL, g_small);
    cudaGetSymbolAddress((void**)&ZU1,   g_zu1);
    cudaGetSymbolAddress((void**)&ZM1,   g_zm1);
    cudaGetSymbolAddress((void**)&ZU2,   g_zu2);
    cudaGetSymbolAddress((void**)&ZM2,   g_zm2);
    cudaGetSymbolAddress((void**)&SS,    g_ss);
    cudaGetSymbolAddress((void**)&SD,    g_sd);
    cudaGetSymbolAddress((void**)&PREU,  g_preu);
    cudaGetSymbolAddress((void**)&PREM,  g_prem);
    cudaGetSymbolAddress((void**)&ROW,   g_row);
    cudaGetSymbolAddress((void**)&CUR,   g_cur);
    cudaGetSymbolAddress((void**)&SSRC,  g_ssrc);
    cudaGetSymbolAddress((void**)&BSUM,  g_bsum);

    // ---- combined CSR build (both directions, one scan) ----
    {
        int nb = (NTOT + 1023) / 1024;
        zero_int<<<(NTOT + 255) / 256, 256>>>(CUR, NTOT);
        count2_k<<<(2 * NE + 255) / 256, 256>>>(um_dst, mu_dst, CUR);
        scan_block<<<nb, 1024>>>(CUR, ROW, BSUM, NTOT);
        scan_bsum<<<1, 128>>>(BSUM, nb);
        add_off<<<nb, 1024>>>(ROW, BSUM, NTOT);
        zero_int<<<(NTOT + 255) / 256, 256>>>(CUR, NTOT);
        scatter2_k<<<(2 * NE + 255) / 256, 256>>>(um_src, um_dst, mu_src, mu_dst,
                                                  ROW, CUR, SSRC);
    }

    // ---- layer 1 ----
    run_gat(xu, NU, FU, xm, NM, FM, ROW, CUR, SSRC,
            w1um_s, w1um_d, a1um_s, a1um_d, b1um,
            H1, C1, ZM1, 1, BIG, SMALL, SS, SD);
    run_gat(xm, NM, FM, xu, NU, FU, ROW + NM, CUR + NM, SSRC,
            w1mu_s, w1mu_d, a1mu_s, a1mu_d, b1mu,
            H1, C1, ZU1, 1, SMALL, BIG, SS, SD);

    // ---- layer 2 ----
    run_gat(ZU1, NU, D1, ZM1, NM, D1, ROW, CUR, SSRC,
            w2um_s, w2um_d, a2um_s, a2um_d, b2um,
            H2, C2, ZM2, 0, BIG, SMALL, SS, SD);
    run_gat(ZM1, NM, D1, ZU1, NU, D1, ROW + NM, CUR + NM, SSRC,
            w2mu_s, w2mu_d, a2mu_s, a2mu_d, b2mu,
            H2, C2, ZU2, 0, SMALL, BIG, SS, SD);

    // ---- edge decoder ----
    pre_kernel<<<(NU + 127) / 128, 128>>>(ZU2, dw1, PREU, NU, 0);
    pre_kernel<<<(NM + 127) / 128, 128>>>(ZM2, dw1, PREM, NM, 512);
    dec_final<<<(NEL + 255) / 256, 256>>>(PREU, PREM, lab_u, lab_m,
                                          db1, dw2, db2, (float*)d_out, NEL);
}

// round 6
// speedup vs baseline: 8.1728x; 1.1776x over previous
#include <cuda_runtime.h>
#include <math.h>

// ---------------- problem constants ----------------
#define NU 100000
#define NM 20000
#define FU 32
#define FM 128
#define H1 8
#define C1 16
#define D1 128   // H1*C1
#define H2 4
#define C2 128
#define D2 512   // H2*C2
#define NE 250000
#define NEL 200000
#define NTOT (NM + NU)   // combined CSR buckets: um dsts [0,NM), mu dsts [NM,NTOT)

// ---------------- device scratch (no runtime alloc allowed) ----------------
__device__ float g_big  [(size_t)NU * D2];   // hs (transformed users)
__device__ float g_small[(size_t)NM * D2];   // hs (transformed movies)
__device__ float g_zu1  [(size_t)NU * D1];
__device__ float g_zm1  [(size_t)NM * D1];
__device__ float g_zu2  [(size_t)NU * D2];
__device__ float g_zm2  [(size_t)NM * D2];
__device__ float g_ssu  [NU * H1];   // src scores, um direction (users)
__device__ float g_sdu  [NU * H1];   // dst scores, mu direction (users)
__device__ float g_ssm  [NM * H1];   // src scores, mu direction (movies)
__device__ float g_sdm  [NM * H1];   // dst scores, um direction (movies)
__device__ float g_preu [(size_t)NU * 16];
__device__ float g_prem [(size_t)NM * 16];
__device__ int g_row [NTOT];
__device__ int g_cur [NTOT];
__device__ int g_ssrc[2 * NE];
__device__ int g_bsum[128];

__device__ __forceinline__ unsigned f2tf(float x) {
    unsigned u;
    asm("cvt.rna.tf32.f32 %0, %1;" : "=r"(u) : "f"(x));
    return u;
}

// ================= TF32 dual-problem GEMM w/ fused attention-score epilogue ==========
// Per problem: C[M,N] = A[M,K] @ B[K,N] (C store skipped if C==null);
//              s[n,h] = sum_c C[n, h*Cd+c] * avec[h*Cd+c].
// blockIdx.z selects problem. N identical across the pair; K%16==0.
#define TBM 128
#define TBN 128
#define TBK 16
#define TPAD 4

struct GP {
    const float* A; const float* B; float* C;
    const float* avec; float* sout;
    int M, K, N, Cd, H;
};

__global__ void __launch_bounds__(256, 2)
gemm_tf32_dual(GP p0, GP p1) {
    const GP p = (blockIdx.z == 0) ? p0 : p1;
    const int row0 = blockIdx.y * TBM;
    if (row0 >= p.M) return;

    __shared__ unsigned As[2][TBK][TBM + TPAD];
    __shared__ unsigned Bs[2][TBK][TBN + TPAD];
    __shared__ float sred[TBM][8];

    const float* __restrict__ A = p.A;
    const float* __restrict__ B = p.B;
    const int M = p.M, N = p.N, K = p.K;

    const int tid  = threadIdx.x;
    const int lane = tid & 31;
    const int wid  = tid >> 5;
    const int col0 = blockIdx.x * TBN;
    const int wm0  = (wid & 1) * 64;
    const int wn0  = (wid >> 1) * 32;
    const int lr   = lane >> 2;
    const int lc   = lane & 3;

    float acc[4][4][4];
#pragma unroll
    for (int mt = 0; mt < 4; mt++)
#pragma unroll
        for (int nt = 0; nt < 4; nt++)
#pragma unroll
            for (int q = 0; q < 4; q++) acc[mt][nt][q] = 0.f;

    float4 aR[2], bR[2];
    const int nkt = K / TBK;

#pragma unroll
    for (int it = 0; it < 2; it++) {
        int idx = tid + it * 256;
        int r = idx >> 2, kq = (idx & 3) * 4;
        int gr = row0 + r;
        aR[it] = make_float4(0.f, 0.f, 0.f, 0.f);
        if (gr < M) aR[it] = *(const float4*)(A + (size_t)gr * K + kq);
        int k = idx >> 5, cq = (idx & 31) * 4;
        bR[it] = *(const float4*)(B + (size_t)k * N + col0 + cq);
    }
#pragma unroll
    for (int it = 0; it < 2; it++) {
        int idx = tid + it * 256;
        int r = idx >> 2, kq = (idx & 3) * 4;
        As[0][kq + 0][r] = f2tf(aR[it].x);
        As[0][kq + 1][r] = f2tf(aR[it].y);
        As[0][kq + 2][r] = f2tf(aR[it].z);
        As[0][kq + 3][r] = f2tf(aR[it].w);
        int k = idx >> 5, cq = (idx & 31) * 4;
        Bs[0][k][cq + 0] = f2tf(bR[it].x);
        Bs[0][k][cq + 1] = f2tf(bR[it].y);
        Bs[0][k][cq + 2] = f2tf(bR[it].z);
        Bs[0][k][cq + 3] = f2tf(bR[it].w);
    }
    __syncthreads();

    for (int t = 0; t < nkt; t++) {
        if (t + 1 < nkt) {
            int k0 = (t + 1) * TBK;
#pragma unroll
            for (int it = 0; it < 2; it++) {
                int idx = tid + it * 256;
                int r = idx >> 2, kq = (idx & 3) * 4;
                int gr = row0 + r;
                aR[it] = make_float4(0.f, 0.f, 0.f, 0.f);
                if (gr < M) aR[it] = *(const float4*)(A + (size_t)gr * K + k0 + kq);
                int k = idx >> 5, cq = (idx & 31) * 4;
                bR[it] = *(const float4*)(B + (size_t)(k0 + k) * N + col0 + cq);
            }
        }
        const int buf = t & 1;
#pragma unroll
        for (int ks = 0; ks < TBK; ks += 8) {
            unsigned af[4][4], bf[4][2];
#pragma unroll
            for (int mt = 0; mt < 4; mt++) {
                int r = wm0 + mt * 16 + lr;
                int c = ks + lc;
                af[mt][0] = As[buf][c][r];
                af[mt][1] = As[buf][c][r + 8];
                af[mt][2] = As[buf][c + 4][r];
                af[mt][3] = As[buf][c + 4][r + 8];
            }
#pragma unroll
            for (int nt = 0; nt < 4; nt++) {
                int n = wn0 + nt * 8 + lr;
                int k = ks + lc;
                bf[nt][0] = Bs[buf][k][n];
                bf[nt][1] = Bs[buf][k + 4][n];
            }
#pragma unroll
            for (int mt = 0; mt < 4; mt++)
#pragma unroll
                for (int nt = 0; nt < 4; nt++) {
                    float* d = acc[mt][nt];
                    asm volatile(
                        "mma.sync.aligned.m16n8k8.row.col.f32.tf32.tf32.f32 "
                        "{%0,%1,%2,%3}, {%4,%5,%6,%7}, {%8,%9}, {%0,%1,%2,%3};\n"
                        : "+f"(d[0]), "+f"(d[1]), "+f"(d[2]), "+f"(d[3])
                        : "r"(af[mt][0]), "r"(af[mt][1]), "r"(af[mt][2]), "r"(af[mt][3]),
                          "r"(bf[nt][0]), "r"(bf[nt][1]));
                }
        }
        if (t + 1 < nkt) {
            const int nb = buf ^ 1;
#pragma unroll
            for (int it = 0; it < 2; it++) {
                int idx = tid + it * 256;
                int r = idx >> 2, kq = (idx & 3) * 4;
                As[nb][kq + 0][r] = f2tf(aR[it].x);
                As[nb][kq + 1][r] = f2tf(aR[it].y);
                As[nb][kq + 2][r] = f2tf(aR[it].z);
                As[nb][kq + 3][r] = f2tf(aR[it].w);
                int k = idx >> 5, cq = (idx & 31) * 4;
                Bs[nb][k][cq + 0] = f2tf(bR[it].x);
                Bs[nb][k][cq + 1] = f2tf(bR[it].y);
                Bs[nb][k][cq + 2] = f2tf(bR[it].z);
                Bs[nb][k][cq + 3] = f2tf(bR[it].w);
            }
            __syncthreads();
        }
    }

    // store C (skipped for dst-side GEMMs whose output feeds only the scores)
    if (p.C) {
        float* C = p.C;
#pragma unroll
        for (int mt = 0; mt < 4; mt++) {
#pragma unroll
            for (int half = 0; half < 2; half++) {
                int gr = row0 + wm0 + mt * 16 + lr + half * 8;
                if (gr < M) {
#pragma unroll
                    for (int nt = 0; nt < 4; nt++) {
                        float2 v = half ? make_float2(acc[mt][nt][2], acc[mt][nt][3])
                                        : make_float2(acc[mt][nt][0], acc[mt][nt][1]);
                        *(float2*)(C + (size_t)gr * N + col0 + wn0 + nt * 8 + lc * 2) = v;
                    }
                }
            }
        }
    }

    // ---- fused score epilogue ----
    {
        const int Cd = p.Cd;
        for (int i = tid; i < TBM * 8; i += 256) ((float*)sred)[i] = 0.f;
        __syncthreads();
        float av0[4], av1[4];
        int grp[4];
        const int hl0 = wn0 / Cd;
        int hb = TBN / Cd; if (hb < 1) hb = 1; if (hb > 8) hb = 8;
#pragma unroll
        for (int nt = 0; nt < 4; nt++) {
            int gc = col0 + wn0 + nt * 8 + lc * 2;
            av0[nt] = __ldg(&p.avec[gc]);
            av1[nt] = __ldg(&p.avec[gc + 1]);
            grp[nt] = (wn0 + nt * 8) / Cd - hl0;
        }
#pragma unroll
        for (int mt = 0; mt < 4; mt++) {
#pragma unroll
            for (int half = 0; half < 2; half++) {
                float pp0 = 0.f, pp1 = 0.f;
#pragma unroll
                for (int nt = 0; nt < 4; nt++) {
                    float v = acc[mt][nt][half * 2] * av0[nt]
                            + acc[mt][nt][half * 2 + 1] * av1[nt];
                    if (grp[nt]) pp1 += v; else pp0 += v;
                }
                pp0 += __shfl_xor_sync(0xffffffffu, pp0, 1);
                pp0 += __shfl_xor_sync(0xffffffffu, pp0, 2);
                pp1 += __shfl_xor_sync(0xffffffffu, pp1, 1);
                pp1 += __shfl_xor_sync(0xffffffffu, pp1, 2);
                if (lc == 0) {
                    int r = wm0 + mt * 16 + lr + half * 8;
                    atomicAdd(&sred[r][hl0], pp0);
                    if (hb > 1) atomicAdd(&sred[r][hl0 + 1], pp1);
                }
            }
        }
        __syncthreads();
        const int hg0 = col0 / Cd;
        for (int i = tid; i < TBM * hb; i += 256) {
            int r = i / hb, hl = i - r * hb;
            int gr = row0 + r;
            if (gr < M) p.sout[(size_t)gr * p.H + hg0 + hl] = sred[r][hl];
        }
    }
}

// ================= combined CSR build kernels =================
__global__ void zero_int(int* __restrict__ p, int n) {
    int i = blockIdx.x * blockDim.x + threadIdx.x;
    if (i < n) p[i] = 0;
}
__global__ void count2_k(const int* __restrict__ um_dst, const int* __restrict__ mu_dst,
                         int* __restrict__ cnt) {
    int i = blockIdx.x * blockDim.x + threadIdx.x;
    if (i >= 2 * NE) return;
    int d = (i < NE) ? um_dst[i] : (NM + mu_dst[i - NE]);
    atomicAdd(&cnt[d], 1);
}
__global__ void scan_block(const int* __restrict__ cnt, int* __restrict__ row,
                           int* __restrict__ bsum, int n) {
    __shared__ int sh[1024];
    int i = blockIdx.x * 1024 + threadIdx.x;
    int v = (i < n) ? cnt[i] : 0;
    sh[threadIdx.x] = v;
    __syncthreads();
    for (int o = 1; o < 1024; o <<= 1) {
        int t = (threadIdx.x >= o) ? sh[threadIdx.x - o] : 0;
        __syncthreads();
        sh[threadIdx.x] += t;
        __syncthreads();
    }
    if (i < n) row[i] = sh[threadIdx.x] - v;
    if (threadIdx.x == 1023) bsum[blockIdx.x] = sh[1023];
}
__global__ void scan_bsum(int* __restrict__ bsum, int nb) {
    __shared__ int sh[128];
    int t = threadIdx.x;
    int v = (t < nb) ? bsum[t] : 0;
    sh[t] = v;
    __syncthreads();
    for (int o = 1; o < 128; o <<= 1) {
        int x = (t >= o) ? sh[t - o] : 0;
        __syncthreads();
        sh[t] += x;
        __syncthreads();
    }
    if (t < nb) bsum[t] = sh[t] - v;
}
__global__ void add_off(int* __restrict__ row, const int* __restrict__ bsum, int n) {
    int i = blockIdx.x * 1024 + threadIdx.x;
    if (i < n) row[i] += bsum[blockIdx.x];
}
__global__ void scatter2_k(const int* __restrict__ um_src, const int* __restrict__ um_dst,
                           const int* __restrict__ mu_src, const int* __restrict__ mu_dst,
                           const int* __restrict__ row, int* __restrict__ cur,
                           int* __restrict__ ssrc) {
    int i = blockIdx.x * blockDim.x + threadIdx.x;
    if (i >= 2 * NE) return;
    int d, s;
    if (i < NE) { d = um_dst[i]; s = um_src[i]; }
    else        { d = NM + mu_dst[i - NE]; s = mu_src[i - NE]; }
    int pos = row[d] + atomicAdd(&cur[d], 1);
    ssrc[pos] = s;
}

// ================= single-pass softmax+aggregate, both directions in one grid =========
// No max-subtraction: scores are O(5), exp is overflow-safe; alpha identical up to ulp.
// No shared memory, no __syncthreads: per-lane redundant sum of exp.
template <int H, int C, bool VEC>
__global__ void __launch_bounds__(128)
gat_agg(const float* __restrict__ hs0, const float* __restrict__ ss0,
        const float* __restrict__ sd0, const float* __restrict__ b0, float* __restrict__ out0,
        const float* __restrict__ hs1, const float* __restrict__ ss1,
        const float* __restrict__ sd1, const float* __restrict__ b1, float* __restrict__ out1,
        const int* __restrict__ row, const int* __restrict__ deg_,
        const int* __restrict__ ssrc, int split, int do_relu) {
    constexpr int D = H * C;
    const int d = blockIdx.x;
    const float *hs, *ss, *sd, *b; float* out; int ld;
    if (d < split) { hs = hs0; ss = ss0; sd = sd0; b = b0; out = out0; ld = d; }
    else           { hs = hs1; ss = ss1; sd = sd1; b = b1; out = out1; ld = d - split; }
    const int start = row[d];
    const int deg = deg_[d];
    const int tid = threadIdx.x;
    const int* sp = ssrc + start;

    if (VEC) {
        // D==512: one float4 per thread; head uniform per warp
        const int h = tid >> 5;
        const float sdd = sd[ld * H + h];
        float4 acc = make_float4(0.f, 0.f, 0.f, 0.f);
        float se = 0.f;
#pragma unroll 2
        for (int k = 0; k < deg; k++) {
            int s = sp[k];
            float v = ss[s * H + h] + sdd;
            v = (v > 0.f) ? v : 0.2f * v;
            float w = __expf(v);
            se += w;
            float4 hv = *(const float4*)(hs + (size_t)s * D + tid * 4);
            acc.x += w * hv.x; acc.y += w * hv.y;
            acc.z += w * hv.z; acc.w += w * hv.w;
        }
        float inv = 1.f / (se + 1e-16f);
        float4 bv = *(const float4*)(b + tid * 4);
        float4 o;
        o.x = acc.x * inv + bv.x; o.y = acc.y * inv + bv.y;
        o.z = acc.z * inv + bv.z; o.w = acc.w * inv + bv.w;
        if (do_relu) {
            o.x = fmaxf(o.x, 0.f); o.y = fmaxf(o.y, 0.f);
            o.z = fmaxf(o.z, 0.f); o.w = fmaxf(o.w, 0.f);
        }
        *(float4*)(out + (size_t)ld * D + tid * 4) = o;
    } else {
        // D==128: one float per thread
        const int h = tid / C;
        const float sdd = sd[ld * H + h];
        float acc = 0.f, se = 0.f;
#pragma unroll 4
        for (int k = 0; k < deg; k++) {
            int s = sp[k];
            float v = ss[s * H + h] + sdd;
            v = (v > 0.f) ? v : 0.2f * v;
            float w = __expf(v);
            se += w;
            acc += w * hs[(size_t)s * D + tid];
        }
        float o = acc / (se + 1e-16f) + b[tid];
        if (do_relu) o = fmaxf(o, 0.f);
        out[(size_t)ld * D + tid] = o;
    }
}

// ================= decoder =================
__global__ void __launch_bounds__(128)
pre_kernel(const float* __restrict__ z, const float* __restrict__ dw1,
           float* __restrict__ pre, int N, int roff) {
    __shared__ float sw[512 * 16];
    const int tid = threadIdx.x;
    for (int i = tid; i < 512 * 16; i += 128) sw[i] = dw1[(size_t)roff * 16 + i];
    __syncthreads();
    int n = blockIdx.x * 128 + tid;
    if (n >= N) return;
    const float4* zp = (const float4*)(z + (size_t)n * 512);
    float acc[16];
#pragma unroll
    for (int j = 0; j < 16; j++) acc[j] = 0.f;
    for (int kq = 0; kq < 128; kq++) {
        float4 zv = zp[kq];
        const float* w0 = &sw[(kq * 4 + 0) * 16];
        const float* w1 = &sw[(kq * 4 + 1) * 16];
        const float* w2 = &sw[(kq * 4 + 2) * 16];
        const float* w3 = &sw[(kq * 4 + 3) * 16];
#pragma unroll
        for (int j = 0; j < 16; j++)
            acc[j] += zv.x * w0[j] + zv.y * w1[j] + zv.z * w2[j] + zv.w * w3[j];
    }
#pragma unroll
    for (int j = 0; j < 16; j++) pre[(size_t)n * 16 + j] = acc[j];
}

__global__ void dec_final(const float* __restrict__ preu, const float* __restrict__ prem,
                          const int* __restrict__ lu, const int* __restrict__ lm,
                          const float* __restrict__ db1, const float* __restrict__ dw2,
                          const float* __restrict__ db2, float* __restrict__ out, int EL) {
    int i = blockIdx.x * blockDim.x + threadIdx.x;
    if (i >= EL) return;
    const float* pu = preu + (size_t)lu[i] * 16;
    const float* pm = prem + (size_t)lm[i] * 16;
    float r = db2[0];
#pragma unroll
    for (int j = 0; j < 16; j++) {
        float h = fmaxf(pu[j] + pm[j] + db1[j], 0.f);
        r += h * dw2[j];
    }
    out[i] = r;
}

// ================= host-side layer driver =================
static void run_layer(const float* xu_in, int Ku, const float* xm_in, int Km,
                      const float* wum_s, const float* wum_d,
                      const float* aum_s, const float* aum_d, const float* bum,
                      const float* wmu_s, const float* wmu_d,
                      const float* amu_s, const float* amu_d, const float* bmu,
                      int H, int C, float* zm_out, float* zu_out, int do_relu,
                      float* BIG, float* SMALL,
                      float* SSU, float* SDM, float* SSM, float* SDU,
                      const int* ROW, const int* CUR, const int* SSRC) {
    int D = H * C;
    dim3 grid(D / TBN, (NU + TBM - 1) / TBM, 2);
    // pair A: um direction (src users -> hs+score; dst movies -> score only)
    GP pa0 = { xu_in, wum_s, BIG,  aum_s, SSU, NU, Ku, D, C, H };
    GP pa1 = { xm_in, wum_d, NULL, aum_d, SDM, NM, Km, D, C, H };
    gemm_tf32_dual<<<grid, 256>>>(pa0, pa1);
    // pair B: mu direction (src movies -> hs+score; dst users -> score only)
    GP pb0 = { xm_in, wmu_s, SMALL, amu_s, SSM, NM, Km, D, C, H };
    GP pb1 = { xu_in, wmu_d, NULL,  amu_d, SDU, NU, Ku, D, C, H };
    gemm_tf32_dual<<<grid, 256>>>(pb0, pb1);

    if (C == 16)
        gat_agg<8, 16, false><<<NTOT, 128>>>(BIG, SSU, SDM, bum, zm_out,
                                             SMALL, SSM, SDU, bmu, zu_out,
                                             ROW, CUR, SSRC, NM, do_relu);
    else
        gat_agg<4, 128, true><<<NTOT, 128>>>(BIG, SSU, SDM, bum, zm_out,
                                             SMALL, SSM, SDU, bmu, zu_out,
                                             ROW, CUR, SSRC, NM, do_relu);
}

extern "C" void kernel_launch(void* const* d_in, const int* in_sizes, int n_in,
                              void* d_out, int out_size) {
    const float* xu     = (const float*)d_in[0];
    const float* xm     = (const float*)d_in[1];
    const int*   um_src = (const int*)d_in[2];
    const int*   um_dst = (const int*)d_in[3];
    const int*   mu_src = (const int*)d_in[4];
    const int*   mu_dst = (const int*)d_in[5];
    const int*   lab_u  = (const int*)d_in[6];
    const int*   lab_m  = (const int*)d_in[7];
    const float* w1um_s = (const float*)d_in[8];
    const float* w1um_d = (const float*)d_in[9];
    const float* a1um_s = (const float*)d_in[10];
    const float* a1um_d = (const float*)d_in[11];
    const float* b1um   = (const float*)d_in[12];
    const float* w1mu_s = (const float*)d_in[13];
    const float* w1mu_d = (const float*)d_in[14];
    const float* a1mu_s = (const float*)d_in[15];
    const float* a1mu_d = (const float*)d_in[16];
    const float* b1mu   = (const float*)d_in[17];
    const float* w2um_s = (const float*)d_in[18];
    const float* w2um_d = (const float*)d_in[19];
    const float* a2um_s = (const float*)d_in[20];
    const float* a2um_d = (const float*)d_in[21];
    const float* b2um   = (const float*)d_in[22];
    const float* w2mu_s = (const float*)d_in[23];
    const float* w2mu_d = (const float*)d_in[24];
    const float* a2mu_s = (const float*)d_in[25];
    const float* a2mu_d = (const float*)d_in[26];
    const float* b2mu   = (const float*)d_in[27];
    const float* dw1    = (const float*)d_in[28];
    const float* db1    = (const float*)d_in[29];
    const float* dw2    = (const float*)d_in[30];
    const float* db2    = (const float*)d_in[31];

    float *BIG, *SMALL, *ZU1, *ZM1, *ZU2, *ZM2, *SSU, *SDU, *SSM, *SDM, *PREU, *PREM;
    int *ROW, *CUR, *SSRC, *BSUM;
    cudaGetSymbolAddress((void**)&BIG,   g_big);
    cudaGetSymbolAddress((void**)&SMALL, g_small);
    cudaGetSymbolAddress((void**)&ZU1,   g_zu1);
    cudaGetSymbolAddress((void**)&ZM1,   g_zm1);
    cudaGetSymbolAddress((void**)&ZU2,   g_zu2);
    cudaGetSymbolAddress((void**)&ZM2,   g_zm2);
    cudaGetSymbolAddress((void**)&SSU,   g_ssu);
    cudaGetSymbolAddress((void**)&SDU,   g_sdu);
    cudaGetSymbolAddress((void**)&SSM,   g_ssm);
    cudaGetSymbolAddress((void**)&SDM,   g_sdm);
    cudaGetSymbolAddress((void**)&PREU,  g_preu);
    cudaGetSymbolAddress((void**)&PREM,  g_prem);
    cudaGetSymbolAddress((void**)&ROW,   g_row);
    cudaGetSymbolAddress((void**)&CUR,   g_cur);
    cudaGetSymbolAddress((void**)&SSRC,  g_ssrc);
    cudaGetSymbolAddress((void**)&BSUM,  g_bsum);

    // ---- combined CSR build ----
    {
        int nb = (NTOT + 1023) / 1024;
        zero_int<<<(NTOT + 255) / 256, 256>>>(CUR, NTOT);
        count2_k<<<(2 * NE + 255) / 256, 256>>>(um_dst, mu_dst, CUR);
        scan_block<<<nb, 1024>>>(CUR, ROW, BSUM, NTOT);
        scan_bsum<<<1, 128>>>(BSUM, nb);
        add_off<<<nb, 1024>>>(ROW, BSUM, NTOT);
        zero_int<<<(NTOT + 255) / 256, 256>>>(CUR, NTOT);
        scatter2_k<<<(2 * NE + 255) / 256, 256>>>(um_src, um_dst, mu_src, mu_dst,
                                                  ROW, CUR, SSRC);
    }

    // ---- layer 1 ----
    run_layer(xu, FU, xm, FM,
              w1um_s, w1um_d, a1um_s, a1um_d, b1um,
              w1mu_s, w1mu_d, a1mu_s, a1mu_d, b1mu,
              H1, C1, ZM1, ZU1, 1,
              BIG, SMALL, SSU, SDM, SSM, SDU, ROW, CUR, SSRC);

    // ---- layer 2 ----
    run_layer(ZU1, D1, ZM1, D1,
              w2um_s, w2um_d, a2um_s, a2um_d, b2um,
              w2mu_s, w2mu_d, a2mu_s, a2mu_d, b2mu,
              H2, C2, ZM2, ZU2, 0,
              BIG, SMALL, SSU, SDM, SSM, SDU, ROW, CUR, SSRC);

    // ---- edge decoder ----
    pre_kernel<<<(NU + 127) / 128, 128>>>(ZU2, dw1, PREU, NU, 0);
    pre_kernel<<<(NM + 127) / 128, 128>>>(ZM2, dw1, PREM, NM, 512);
    dec_final<<<(NEL + 255) / 256, 256>>>(PREU, PREM, lab_u, lab_m,
                                          db1, dw2, db2, (float*)d_out, NEL);
}

// round 11
// speedup vs baseline: 15.5586x; 1.9037x over previous
#include <cuda_runtime.h>
#include <math.h>

// ---------------- problem constants ----------------
#define NU 100000
#define NM 20000
#define FU 32
#define FM 128
#define H1 8
#define C1 16
#define D1 128
#define H2 4
#define C2 128
#define D2 512
#define NE 250000
#define NEL 200000
#define NTOT (NM + NU)   // combined CSR buckets: um dsts [0,NM), mu dsts [NM,NTOT)

// ---------------- device scratch ----------------
__device__ float g_zu1  [(size_t)NU * D1];
__device__ float g_zm1  [(size_t)NM * D1];
__device__ float g_hsmu1[(size_t)NM * D1];     // xm @ w1mu_s
__device__ float g_Pu   [(size_t)NU * 128];    // zu1 @ Bu  (cols 0-63 proj, 64-71 scores)
__device__ float g_Pm   [(size_t)NM * 128];    // zm1 @ Bm
__device__ float g_s1u  [NU * 16];             // xu scores: 0-7 um_src, 8-15 mu_dst
__device__ float g_s1m  [NM * 16];             // xm scores: 0-7 mu_src, 8-15 um_dst
__device__ float g_preu [(size_t)NU * 16];
__device__ float g_prem [(size_t)NM * 16];
__device__ float g_Qu[32 * 16];
__device__ float g_Qm[128 * 16];
__device__ float g_Bu[128 * 128];
__device__ float g_Bm[128 * 128];
__device__ float g_cm[16];
__device__ float g_cu[16];
__device__ int g_row [NTOT];
__device__ int g_cur [NTOT];
__device__ int g_ssrc[2 * NE];
__device__ int g_bsum[128];

__device__ __forceinline__ unsigned f2tf(float x) {
    unsigned u;
    asm("cvt.rna.tf32.f32 %0, %1;" : "=r"(u) : "f"(x));
    return u;
}

// ================= TF32 dual GEMM: C[M,128] = A[M,128] @ B[128,128] =================
#define TBM 128
#define TBK 16
#define TPAD 4

struct GP { const float* A; const float* B; float* C; int M; };

__global__ void __launch_bounds__(256, 2)
gemm_dual(GP p0, GP p1) {
    const GP p = (blockIdx.z == 0) ? p0 : p1;
    const int row0 = blockIdx.y * TBM;
    if (row0 >= p.M) return;

    __shared__ unsigned As[2][TBK][TBM + TPAD];
    __shared__ unsigned Bs[2][TBK][128 + TPAD];

    const float* __restrict__ A = p.A;
    const float* __restrict__ B = p.B;
    const int M = p.M;
    const int K = 128, N = 128;

    const int tid  = threadIdx.x;
    const int lane = tid & 31;
    const int wid  = tid >> 5;
    const int wm0  = (wid & 1) * 64;
    const int wn0  = (wid >> 1) * 32;
    const int lr   = lane >> 2;
    const int lc   = lane & 3;

    float acc[4][4][4];
#pragma unroll
    for (int mt = 0; mt < 4; mt++)
#pragma unroll
        for (int nt = 0; nt < 4; nt++)
#pragma unroll
            for (int q = 0; q < 4; q++) acc[mt][nt][q] = 0.f;

    float4 aR[2], bR[2];
    const int nkt = K / TBK;   // 8

#pragma unroll
    for (int it = 0; it < 2; it++) {
        int idx = tid + it * 256;
        int r = idx >> 2, kq = (idx & 3) * 4;
        int gr = row0 + r;
        aR[it] = make_float4(0.f, 0.f, 0.f, 0.f);
        if (gr < M) aR[it] = *(const float4*)(A + (size_t)gr * K + kq);
        int k = idx >> 5, cq = (idx & 31) * 4;
        bR[it] = *(const float4*)(B + (size_t)k * N + cq);
    }
#pragma unroll
    for (int it = 0; it < 2; it++) {
        int idx = tid + it * 256;
        int r = idx >> 2, kq = (idx & 3) * 4;
        As[0][kq + 0][r] = f2tf(aR[it].x);
        As[0][kq + 1][r] = f2tf(aR[it].y);
        As[0][kq + 2][r] = f2tf(aR[it].z);
        As[0][kq + 3][r] = f2tf(aR[it].w);
        int k = idx >> 5, cq = (idx & 31) * 4;
        Bs[0][k][cq + 0] = f2tf(bR[it].x);
        Bs[0][k][cq + 1] = f2tf(bR[it].y);
        Bs[0][k][cq + 2] = f2tf(bR[it].z);
        Bs[0][k][cq + 3] = f2tf(bR[it].w);
    }
    __syncthreads();

    for (int t = 0; t < nkt; t++) {
        if (t + 1 < nkt) {
            int k0 = (t + 1) * TBK;
#pragma unroll
            for (int it = 0; it < 2; it++) {
                int idx = tid + it * 256;
                int r = idx >> 2, kq = (idx & 3) * 4;
                int gr = row0 + r;
                aR[it] = make_float4(0.f, 0.f, 0.f, 0.f);
                if (gr < M) aR[it] = *(const float4*)(A + (size_t)gr * K + k0 + kq);
                int k = idx >> 5, cq = (idx & 31) * 4;
                bR[it] = *(const float4*)(B + (size_t)(k0 + k) * N + cq);
            }
        }
        const int buf = t & 1;
#pragma unroll
        for (int ks = 0; ks < TBK; ks += 8) {
            unsigned af[4][4], bf[4][2];
#pragma unroll
            for (int mt = 0; mt < 4; mt++) {
                int r = wm0 + mt * 16 + lr;
                int c = ks + lc;
                af[mt][0] = As[buf][c][r];
                af[mt][1] = As[buf][c][r + 8];
                af[mt][2] = As[buf][c + 4][r];
                af[mt][3] = As[buf][c + 4][r + 8];
            }
#pragma unroll
            for (int nt = 0; nt < 4; nt++) {
                int n = wn0 + nt * 8 + lr;
                int k = ks + lc;
                bf[nt][0] = Bs[buf][k][n];
                bf[nt][1] = Bs[buf][k + 4][n];
            }
#pragma unroll
            for (int mt = 0; mt < 4; mt++)
#pragma unroll
                for (int nt = 0; nt < 4; nt++) {
                    float* d = acc[mt][nt];
                    asm volatile(
                        "mma.sync.aligned.m16n8k8.row.col.f32.tf32.tf32.f32 "
                        "{%0,%1,%2,%3}, {%4,%5,%6,%7}, {%8,%9}, {%0,%1,%2,%3};\n"
                        : "+f"(d[0]), "+f"(d[1]), "+f"(d[2]), "+f"(d[3])
                        : "r"(af[mt][0]), "r"(af[mt][1]), "r"(af[mt][2]), "r"(af[mt][3]),
                          "r"(bf[nt][0]), "r"(bf[nt][1]));
                }
        }
        if (t + 1 < nkt) {
            const int nb = buf ^ 1;
#pragma unroll
            for (int it = 0; it < 2; it++) {
                int idx = tid + it * 256;
                int r = idx >> 2, kq = (idx & 3) * 4;
                As[nb][kq + 0][r] = f2tf(aR[it].x);
                As[nb][kq + 1][r] = f2tf(aR[it].y);
                As[nb][kq + 2][r] = f2tf(aR[it].z);
                As[nb][kq + 3][r] = f2tf(aR[it].w);
                int k = idx >> 5, cq = (idx & 31) * 4;
                Bs[nb][k][cq + 0] = f2tf(bR[it].x);
                Bs[nb][k][cq + 1] = f2tf(bR[it].y);
                Bs[nb][k][cq + 2] = f2tf(bR[it].z);
                Bs[nb][k][cq + 3] = f2tf(bR[it].w);
            }
            __syncthreads();
        }
    }
    float* C = p.C;
#pragma unroll
    for (int mt = 0; mt < 4; mt++) {
#pragma unroll
        for (int half = 0; half < 2; half++) {
            int gr = row0 + wm0 + mt * 16 + lr + half * 8;
            if (gr < M) {
#pragma unroll
                for (int nt = 0; nt < 4; nt++) {
                    float2 v = half ? make_float2(acc[mt][nt][2], acc[mt][nt][3])
                                    : make_float2(acc[mt][nt][0], acc[mt][nt][1]);
                    *(float2*)(C + (size_t)gr * 128 + wn0 + nt * 8 + lc * 2) = v;
                }
            }
        }
    }
}

// ================= compose kernels (fp32, tiny) =================
// Qu[32][16]: j<8: q1um_s[k,h]=sum_c w1um_s[k,h*16+c]*a1um_s[h,c]; j>=8: q1mu_d
// Qm[128][16]: j<8: q1mu_s; j>=8: q1um_d
__global__ void compose_q1(const float* __restrict__ w1um_s, const float* __restrict__ a1um_s,
                           const float* __restrict__ w1mu_d, const float* __restrict__ a1mu_d,
                           const float* __restrict__ w1mu_s, const float* __restrict__ a1mu_s,
                           const float* __restrict__ w1um_d, const float* __restrict__ a1um_d,
                           float* __restrict__ Qu, float* __restrict__ Qm) {
    int t = blockIdx.x * blockDim.x + threadIdx.x;
    if (t < 32 * 16) {
        int k = t >> 4, j = t & 15, h = j & 7;
        const float* W = (j < 8) ? w1um_s : w1mu_d;
        const float* a = (j < 8) ? a1um_s : a1mu_d;
        float acc = 0.f;
        for (int c = 0; c < 16; c++) acc += W[k * 128 + h * 16 + c] * a[h * 16 + c];
        Qu[t] = acc;
    } else if (t < 32 * 16 + 128 * 16) {
        int tt = t - 512;
        int k = tt >> 4, j = tt & 15, h = j & 7;
        const float* W = (j < 8) ? w1mu_s : w1um_d;
        const float* a = (j < 8) ? a1mu_s : a1um_d;
        float acc = 0.f;
        for (int c = 0; c < 16; c++) acc += W[k * 128 + h * 16 + c] * a[h * 16 + c];
        Qm[tt] = acc;
    }
}

// Bu[128][128]: cols 0-63 T_um (w2um_s x dw1[512:1024]), 64-67 q2um_s, 68-71 q2mu_d, rest 0
// Bm[128][128]: cols 0-63 T_mu (w2mu_s x dw1[0:512]),   64-67 q2mu_s, 68-71 q2um_d, rest 0
// cm[16]=b2um@dw1[512:], cu[16]=b2mu@dw1[:512]
__global__ void compose_B(const float* __restrict__ w2um_s, const float* __restrict__ a2um_s,
                          const float* __restrict__ w2mu_d, const float* __restrict__ a2mu_d,
                          const float* __restrict__ w2mu_s, const float* __restrict__ a2mu_s,
                          const float* __restrict__ w2um_d, const float* __restrict__ a2um_d,
                          const float* __restrict__ dw1,
                          const float* __restrict__ b2um, const float* __restrict__ b2mu,
                          float* __restrict__ Bu, float* __restrict__ Bm,
                          float* __restrict__ cm, float* __restrict__ cu) {
    int t = blockIdx.x * blockDim.x + threadIdx.x;
    if (t < 32768) {
        int which = t >> 14;
        int tt = t & 16383;
        int k = tt >> 7, j = tt & 127;
        float acc = 0.f;
        if (which == 0) {
            if (j < 64) {
                int h = j >> 4, jj = j & 15;
                for (int i = 0; i < 128; i++)
                    acc += w2um_s[k * 512 + h * 128 + i] * dw1[(size_t)(512 + h * 128 + i) * 16 + jj];
            } else if (j < 68) {
                int h = j - 64;
                for (int c = 0; c < 128; c++) acc += w2um_s[k * 512 + h * 128 + c] * a2um_s[h * 128 + c];
            } else if (j < 72) {
                int h = j - 68;
                for (int c = 0; c < 128; c++) acc += w2mu_d[k * 512 + h * 128 + c] * a2mu_d[h * 128 + c];
            }
            Bu[tt] = acc;
        } else {
            if (j < 64) {
                int h = j >> 4, jj = j & 15;
                for (int i = 0; i < 128; i++)
                    acc += w2mu_s[k * 512 + h * 128 + i] * dw1[(size_t)(h * 128 + i) * 16 + jj];
            } else if (j < 68) {
                int h = j - 64;
                for (int c = 0; c < 128; c++) acc += w2mu_s[k * 512 + h * 128 + c] * a2mu_s[h * 128 + c];
            } else if (j < 72) {
                int h = j - 68;
                for (int c = 0; c < 128; c++) acc += w2um_d[k * 512 + h * 128 + c] * a2um_d[h * 128 + c];
            }
            Bm[tt] = acc;
        }
    } else if (t < 32768 + 32) {
        int j = t - 32768;
        if (j < 16) {
            float acc = 0.f;
            for (int i = 0; i < 512; i++) acc += b2um[i] * dw1[(size_t)(512 + i) * 16 + j];
            cm[j] = acc;
        } else {
            int jj = j - 16;
            float acc = 0.f;
            for (int i = 0; i < 512; i++) acc += b2mu[i] * dw1[(size_t)i * 16 + jj];
            cu[jj] = acc;
        }
    }
}

// ================= node scores: s[n,0:16] = x[n,:] @ Q[K,16] (warp per node) =========
template <int K>
__global__ void score_k(const float* __restrict__ x, const float* __restrict__ Q,
                        float* __restrict__ s, int N) {
    int warp = (blockIdx.x * blockDim.x + threadIdx.x) >> 5;
    int lane = threadIdx.x & 31;
    if (warp >= N) return;
    float p[16];
#pragma unroll
    for (int j = 0; j < 16; j++) p[j] = 0.f;
    const float* xr = x + (size_t)warp * K;
#pragma unroll
    for (int kk = 0; kk < K / 32; kk++) {
        int k = kk * 32 + lane;
        float xv = xr[k];
        const float4* q4 = (const float4*)(Q + k * 16);
        float4 q0 = q4[0], q1 = q4[1], q2 = q4[2], q3 = q4[3];
        p[0] += xv * q0.x; p[1] += xv * q0.y; p[2]  += xv * q0.z; p[3]  += xv * q0.w;
        p[4] += xv * q1.x; p[5] += xv * q1.y; p[6]  += xv * q1.z; p[7]  += xv * q1.w;
        p[8] += xv * q2.x; p[9] += xv * q2.y; p[10] += xv * q2.z; p[11] += xv * q2.w;
        p[12]+= xv * q3.x; p[13]+= xv * q3.y; p[14] += xv * q3.z; p[15] += xv * q3.w;
    }
#pragma unroll
    for (int j = 0; j < 16; j++)
#pragma unroll
        for (int o = 16; o; o >>= 1) p[j] += __shfl_xor_sync(0xffffffffu, p[j], o);
    if (lane == 0) {
        float4* sp = (float4*)(s + (size_t)warp * 16);
        sp[0] = make_float4(p[0], p[1], p[2], p[3]);
        sp[1] = make_float4(p[4], p[5], p[6], p[7]);
        sp[2] = make_float4(p[8], p[9], p[10], p[11]);
        sp[3] = make_float4(p[12], p[13], p[14], p[15]);
    }
}

// ================= CSR build =================
__global__ void zero_int(int* __restrict__ p, int n) {
    int i = blockIdx.x * blockDim.x + threadIdx.x;
    if (i < n) p[i] = 0;
}
__global__ void count2_k(const int* __restrict__ um_dst, const int* __restrict__ mu_dst,
                         int* __restrict__ cnt) {
    int i = blockIdx.x * blockDim.x + threadIdx.x;
    if (i >= 2 * NE) return;
    int d = (i < NE) ? um_dst[i] : (NM + mu_dst[i - NE]);
    atomicAdd(&cnt[d], 1);
}
__global__ void scan_block(const int* __restrict__ cnt, int* __restrict__ row,
                           int* __restrict__ bsum, int n) {
    __shared__ int sh[1024];
    int i = blockIdx.x * 1024 + threadIdx.x;
    int v = (i < n) ? cnt[i] : 0;
    sh[threadIdx.x] = v;
    __syncthreads();
    for (int o = 1; o < 1024; o <<= 1) {
        int t = (threadIdx.x >= o) ? sh[threadIdx.x - o] : 0;
        __syncthreads();
        sh[threadIdx.x] += t;
        __syncthreads();
    }
    if (i < n) row[i] = sh[threadIdx.x] - v;
    if (threadIdx.x == 1023) bsum[blockIdx.x] = sh[1023];
}
__global__ void scan_bsum(int* __restrict__ bsum, int nb) {
    __shared__ int sh[128];
    int t = threadIdx.x;
    int v = (t < nb) ? bsum[t] : 0;
    sh[t] = v;
    __syncthreads();
    for (int o = 1; o < 128; o <<= 1) {
        int x = (t >= o) ? sh[t - o] : 0;
        __syncthreads();
        sh[t] += x;
        __syncthreads();
    }
    if (t < nb) bsum[t] = sh[t] - v;
}
__global__ void add_off(int* __restrict__ row, const int* __restrict__ bsum,
                        int* __restrict__ cur, int n) {
    int i = blockIdx.x * 1024 + threadIdx.x;
    if (i < n) { row[i] += bsum[blockIdx.x]; cur[i] = 0; }
}
__global__ void scatter2_k(const int* __restrict__ um_src, const int* __restrict__ um_dst,
                           const int* __restrict__ mu_src, const int* __restrict__ mu_dst,
                           const int* __restrict__ row, int* __restrict__ cur,
                           int* __restrict__ ssrc) {
    int i = blockIdx.x * blockDim.x + threadIdx.x;
    if (i >= 2 * NE) return;
    int d, s;
    if (i < NE) { d = um_dst[i]; s = um_src[i]; }
    else        { d = NM + mu_dst[i - NE]; s = mu_src[i - NE]; }
    int pos = row[d] + atomicAdd(&cur[d], 1);
    ssrc[pos] = s;
}

// ================= L1 um: per-head raw aggregation + fused 32->16 transform ==========
// block 256 = 8 warps; warp = head h, lane = input feature k (FU=32)
__global__ void __launch_bounds__(256)
agg1_um(const float* __restrict__ xu, const float* __restrict__ s1u,
        const float* __restrict__ s1m, const float* __restrict__ w1um_s,
        const float* __restrict__ b1um, float* __restrict__ zm1,
        const int* __restrict__ row, const int* __restrict__ deg_,
        const int* __restrict__ ssrc) {
    int d = blockIdx.x;
    int h = threadIdx.x >> 5;
    int k = threadIdx.x & 31;
    int start = row[d], deg = deg_[d];
    const int* sp = ssrc + start;
    float sdd = s1m[d * 16 + 8 + h];
    float acc = 0.f, se = 0.f;
    for (int e = 0; e < deg; e++) {
        int s = sp[e];
        float v = s1u[s * 16 + h] + sdd;
        v = (v > 0.f) ? v : 0.2f * v;
        float w = __expf(v);
        se += w;
        acc += w * xu[(size_t)s * FU + k];
    }
    float agg = acc / (se + 1e-16f);
    const float4* w4 = (const float4*)(w1um_s + k * 128 + h * 16);
    float4 w0 = w4[0], w1 = w4[1], w2 = w4[2], w3 = w4[3];
    float p[16];
    p[0] = agg * w0.x; p[1] = agg * w0.y; p[2]  = agg * w0.z; p[3]  = agg * w0.w;
    p[4] = agg * w1.x; p[5] = agg * w1.y; p[6]  = agg * w1.z; p[7]  = agg * w1.w;
    p[8] = agg * w2.x; p[9] = agg * w2.y; p[10] = agg * w2.z; p[11] = agg * w2.w;
    p[12]= agg * w3.x; p[13]= agg * w3.y; p[14] = agg * w3.z; p[15] = agg * w3.w;
#pragma unroll
    for (int j = 0; j < 16; j++)
#pragma unroll
        for (int o = 16; o; o >>= 1) p[j] += __shfl_xor_sync(0xffffffffu, p[j], o);
    if (k == 0) {
        float* out = zm1 + (size_t)d * 128 + h * 16;
        const float* b = b1um + h * 16;
#pragma unroll
        for (int j = 0; j < 16; j++) out[j] = fmaxf(p[j] + b[j], 0.f);
    }
}

// ================= L1 mu: standard D=128 aggregation over hs_mu1 =================
__global__ void __launch_bounds__(128)
agg1_mu(const float* __restrict__ hs, const float* __restrict__ s1m,
        const float* __restrict__ s1u, const float* __restrict__ b1mu,
        float* __restrict__ zu1, const int* __restrict__ row,
        const int* __restrict__ deg_, const int* __restrict__ ssrc) {
    int d = blockIdx.x;   // user index; caller passes row/deg offset by NM
    int tid = threadIdx.x;
    int h = tid >> 4;
    int start = row[d], deg = deg_[d];
    const int* sp = ssrc + start;
    float sdd = s1u[d * 16 + 8 + h];
    float acc = 0.f, se = 0.f;
#pragma unroll 4
    for (int e = 0; e < deg; e++) {
        int s = sp[e];
        float v = s1m[s * 16 + h] + sdd;
        v = (v > 0.f) ? v : 0.2f * v;
        float w = __expf(v);
        se += w;
        acc += w * hs[(size_t)s * 128 + tid];
    }
    zu1[(size_t)d * 128 + tid] = fmaxf(acc / (se + 1e-16f) + b1mu[tid], 0.f);
}

// ================= L2: fused aggregation + decoder pre (both directions) =============
// block 64 threads: t = h*16+jj; gathers P rows (cols 0-63 proj, 64+h src score)
__global__ void __launch_bounds__(64)
agg2(const float* __restrict__ Pu, const float* __restrict__ Pm,
     const float* __restrict__ cm, const float* __restrict__ cu,
     float* __restrict__ prem, float* __restrict__ preu,
     const int* __restrict__ row, const int* __restrict__ deg_,
     const int* __restrict__ ssrc) {
    __shared__ float red[16];
    int d = blockIdx.x;
    const float *Psrc, *Pdrow, *c; float* out; int ld;
    if (d < NM) { Psrc = Pu; c = cm; out = prem; ld = d;      Pdrow = Pm + (size_t)d * 128; }
    else        { Psrc = Pm; c = cu; out = preu; ld = d - NM; Pdrow = Pu + (size_t)ld * 128; }
    int t = threadIdx.x;
    int h = t >> 4, jj = t & 15;
    int start = row[d], deg = deg_[d];
    const int* sp = ssrc + start;
    float sdd = Pdrow[68 + h];
    float acc = 0.f, se = 0.f;
#pragma unroll 2
    for (int e = 0; e < deg; e++) {
        int s = sp[e];
        const float* pr = Psrc + (size_t)s * 128;
        float v = pr[64 + h] + sdd;
        v = (v > 0.f) ? v : 0.2f * v;
        float w = __expf(v);
        se += w;
        acc += w * pr[t];
    }
    float val = acc / (se + 1e-16f);
    if (t < 16) red[t] = 0.f;
    __syncthreads();
    atomicAdd(&red[jj], val);
    __syncthreads();
    if (t < 16) out[(size_t)ld * 16 + t] = red[t] + c[t];
}

// ================= decoder final =================
__global__ void dec_final(const float* __restrict__ preu, const float* __restrict__ prem,
                          const int* __restrict__ lu, const int* __restrict__ lm,
                          const float* __restrict__ db1, const float* __restrict__ dw2,
                          const float* __restrict__ db2, float* __restrict__ out, int EL) {
    int i = blockIdx.x * blockDim.x + threadIdx.x;
    if (i >= EL) return;
    const float* pu = preu + (size_t)lu[i] * 16;
    const float* pm = prem + (size_t)lm[i] * 16;
    float r = db2[0];
#pragma unroll
    for (int j = 0; j < 16; j++) {
        float h = fmaxf(pu[j] + pm[j] + db1[j], 0.f);
        r += h * dw2[j];
    }
    out[i] = r;
}

extern "C" void kernel_launch(void* const* d_in, const int* in_sizes, int n_in,
                              void* d_out, int out_size) {
    const float* xu     = (const float*)d_in[0];
    const float* xm     = (const float*)d_in[1];
    const int*   um_src = (const int*)d_in[2];
    const int*   um_dst = (const int*)d_in[3];
    const int*   mu_src = (const int*)d_in[4];
    const int*   mu_dst = (const int*)d_in[5];
    const int*   lab_u  = (const int*)d_in[6];
    const int*   lab_m  = (const int*)d_in[7];
    const float* w1um_s = (const float*)d_in[8];
    const float* w1um_d = (const float*)d_in[9];
    const float* a1um_s = (const float*)d_in[10];
    const float* a1um_d = (const float*)d_in[11];
    const float* b1um   = (const float*)d_in[12];
    const float* w1mu_s = (const float*)d_in[13];
    const float* w1mu_d = (const float*)d_in[14];
    const float* a1mu_s = (const float*)d_in[15];
    const float* a1mu_d = (const float*)d_in[16];
    const float* b1mu   = (const float*)d_in[17];
    const float* w2um_s = (const float*)d_in[18];
    const float* w2um_d = (const float*)d_in[19];
    const float* a2um_s = (const float*)d_in[20];
    const float* a2um_d = (const float*)d_in[21];
    const float* b2um   = (const float*)d_in[22];
    const float* w2mu_s = (const float*)d_in[23];
    const float* w2mu_d = (const float*)d_in[24];
    const float* a2mu_s = (const float*)d_in[25];
    const float* a2mu_d = (const float*)d_in[26];
    const float* b2mu   = (const float*)d_in[27];
    const float* dw1    = (const float*)d_in[28];
    const float* db1    = (const float*)d_in[29];
    const float* dw2    = (const float*)d_in[30];
    const float* db2    = (const float*)d_in[31];

    float *ZU1, *ZM1, *HSMU1, *PU, *PM, *S1U, *S1M, *PREU, *PREM;
    float *QU, *QM, *BU, *BM, *CM, *CU;
    int *ROW, *CUR, *SSRC, *BSUM;
    cudaGetSymbolAddress((void**)&ZU1,   g_zu1);
    cudaGetSymbolAddress((void**)&ZM1,   g_zm1);
    cudaGetSymbolAddress((void**)&HSMU1, g_hsmu1);
    cudaGetSymbolAddress((void**)&PU,    g_Pu);
    cudaGetSymbolAddress((void**)&PM,    g_Pm);
    cudaGetSymbolAddress((void**)&S1U,   g_s1u);
    cudaGetSymbolAddress((void**)&S1M,   g_s1m);
    cudaGetSymbolAddress((void**)&PREU,  g_preu);
    cudaGetSymbolAddress((void**)&PREM,  g_prem);
    cudaGetSymbolAddress((void**)&QU,    g_Qu);
    cudaGetSymbolAddress((void**)&QM,    g_Qm);
    cudaGetSymbolAddress((void**)&BU,    g_Bu);
    cudaGetSymbolAddress((void**)&BM,    g_Bm);
    cudaGetSymbolAddress((void**)&CM,    g_cm);
    cudaGetSymbolAddress((void**)&CU,    g_cu);
    cudaGetSymbolAddress((void**)&ROW,   g_row);
    cudaGetSymbolAddress((void**)&CUR,   g_cur);
    cudaGetSymbolAddress((void**)&SSRC,  g_ssrc);
    cudaGetSymbolAddress((void**)&BSUM,  g_bsum);

    // ---- combined CSR build ----
    {
        int nb = (NTOT + 1023) / 1024;
        zero_int<<<(NTOT + 255) / 256, 256>>>(CUR, NTOT);
        count2_k<<<(2 * NE + 255) / 256, 256>>>(um_dst, mu_dst, CUR);
        scan_block<<<nb, 1024>>>(CUR, ROW, BSUM, NTOT);
        scan_bsum<<<1, 128>>>(BSUM, nb);
        add_off<<<nb, 1024>>>(ROW, BSUM, CUR, NTOT);
        scatter2_k<<<(2 * NE + 255) / 256, 256>>>(um_src, um_dst, mu_src, mu_dst,
                                                  ROW, CUR, SSRC);
    }

    // ---- weight compositions (independent of graph) ----
    compose_q1<<<10, 256>>>(w1um_s, a1um_s, w1mu_d, a1mu_d,
                            w1mu_s, a1mu_s, w1um_d, a1um_d, QU, QM);
    compose_B<<<(32800 + 255) / 256, 256>>>(w2um_s, a2um_s, w2mu_d, a2mu_d,
                                            w2mu_s, a2mu_s, w2um_d, a2um_d,
                                            dw1, b2um, b2mu, BU, BM, CM, CU);

    // ---- layer-1 node scores (pure fp32) ----
    score_k<32><<<(NU * 32 + 255) / 256, 256>>>(xu, QU, S1U, NU);
    score_k<128><<<(NM * 32 + 255) / 256, 256>>>(xm, QM, S1M, NM);

    // ---- hs for mu direction: xm @ w1mu_s ----
    {
        GP pa = { xm, w1mu_s, HSMU1, NM };
        dim3 grid(1, (NM + TBM - 1) / TBM, 1);
        gemm_dual<<<grid, 256>>>(pa, pa);
    }

    // ---- layer-1 aggregation ----
    agg1_um<<<NM, 256>>>(xu, S1U, S1M, w1um_s, b1um, ZM1, ROW, CUR, SSRC);
    agg1_mu<<<NU, 128>>>(HSMU1, S1M, S1U, b1mu, ZU1, ROW + NM, CUR + NM, SSRC);

    // ---- layer-2 projections: P = z1 @ B (proj cols 0-63, scores 64-71) ----
    {
        GP p0 = { ZU1, BU, PU, NU };
        GP p1 = { ZM1, BM, PM, NM };
        dim3 grid(1, (NU + TBM - 1) / TBM, 2);
        gemm_dual<<<grid, 256>>>(p0, p1);
    }

    // ---- layer-2 aggregation fused with decoder pre-projection ----
    agg2<<<NTOT, 64>>>(PU, PM, CM, CU, PREM, PREU, ROW, CUR, SSRC);

    // ---- decoder final ----
    dec_final<<<(NEL + 255) / 256, 256>>>(PREU, PREM, lab_u, lab_m,
                                          db1, dw2, db2, (float*)d_out, NEL);
}

// round 16
// speedup vs baseline: 15.8877x; 1.0212x over previous
#include <cuda_runtime.h>
#include <math.h>

// ---------------- problem constants ----------------
#define NU 100000
#define NM 20000
#define FU 32
#define FM 128
#define H1 8
#define C1 16
#define D1 128
#define H2 4
#define C2 128
#define D2 512
#define NE 250000
#define NEL 200000
#define NTOT (NM + NU)   // combined CSR buckets: um dsts [0,NM), mu dsts [NM,NTOT)

// ---------------- device scratch ----------------
__device__ float g_zu1  [(size_t)NU * D1];
__device__ float g_zm1  [(size_t)NM * D1];
__device__ float g_hsmu1[(size_t)NM * D1];     // xm @ w1mu_s
__device__ float g_Pu   [(size_t)NU * 128];    // zu1 @ Bu  (cols 0-63 proj, 64-71 scores)
__device__ float g_Pm   [(size_t)NM * 128];    // zm1 @ Bm
__device__ float g_s1u  [NU * 16];             // xu scores: 0-7 um_src, 8-15 mu_dst
__device__ float g_s1m  [NM * 16];             // xm scores: 0-7 mu_src, 8-15 um_dst
__device__ float g_preu [(size_t)NU * 16];
__device__ float g_prem [(size_t)NM * 16];
__device__ float g_Qu[32 * 16];
__device__ float g_Qm[128 * 16];
__device__ float g_Bu[128 * 128];
__device__ float g_Bm[128 * 128];
__device__ float g_cm[16];
__device__ float g_cu[16];
__device__ int g_row [NTOT];
__device__ int g_cur [NTOT];
__device__ int g_ssrc[2 * NE];
__device__ int g_bsum[128];

__device__ __forceinline__ unsigned f2tf(float x) {
    unsigned u;
    asm("cvt.rna.tf32.f32 %0, %1;" : "=r"(u) : "f"(x));
    return u;
}

// ================= TF32 dual GEMM: C[M,128] = A[M,128] @ B[128,128] =================
#define TBM 128
#define TBK 16
#define TPAD 4

struct GP { const float* A; const float* B; float* C; int M; };

__global__ void __launch_bounds__(256, 2)
gemm_dual(GP p0, GP p1) {
    const GP p = (blockIdx.z == 0) ? p0 : p1;
    const int row0 = blockIdx.y * TBM;
    if (row0 >= p.M) return;

    __shared__ unsigned As[2][TBK][TBM + TPAD];
    __shared__ unsigned Bs[2][TBK][128 + TPAD];

    const float* __restrict__ A = p.A;
    const float* __restrict__ B = p.B;
    const int M = p.M;
    const int K = 128, N = 128;

    const int tid  = threadIdx.x;
    const int lane = tid & 31;
    const int wid  = tid >> 5;
    const int wm0  = (wid & 1) * 64;
    const int wn0  = (wid >> 1) * 32;
    const int lr   = lane >> 2;
    const int lc   = lane & 3;

    float acc[4][4][4];
#pragma unroll
    for (int mt = 0; mt < 4; mt++)
#pragma unroll
        for (int nt = 0; nt < 4; nt++)
#pragma unroll
            for (int q = 0; q < 4; q++) acc[mt][nt][q] = 0.f;

    float4 aR[2], bR[2];
    const int nkt = K / TBK;   // 8

#pragma unroll
    for (int it = 0; it < 2; it++) {
        int idx = tid + it * 256;
        int r = idx >> 2, kq = (idx & 3) * 4;
        int gr = row0 + r;
        aR[it] = make_float4(0.f, 0.f, 0.f, 0.f);
        if (gr < M) aR[it] = *(const float4*)(A + (size_t)gr * K + kq);
        int k = idx >> 5, cq = (idx & 31) * 4;
        bR[it] = *(const float4*)(B + (size_t)k * N + cq);
    }
#pragma unroll
    for (int it = 0; it < 2; it++) {
        int idx = tid + it * 256;
        int r = idx >> 2, kq = (idx & 3) * 4;
        As[0][kq + 0][r] = f2tf(aR[it].x);
        As[0][kq + 1][r] = f2tf(aR[it].y);
        As[0][kq + 2][r] = f2tf(aR[it].z);
        As[0][kq + 3][r] = f2tf(aR[it].w);
        int k = idx >> 5, cq = (idx & 31) * 4;
        Bs[0][k][cq + 0] = f2tf(bR[it].x);
        Bs[0][k][cq + 1] = f2tf(bR[it].y);
        Bs[0][k][cq + 2] = f2tf(bR[it].z);
        Bs[0][k][cq + 3] = f2tf(bR[it].w);
    }
    __syncthreads();

    for (int t = 0; t < nkt; t++) {
        if (t + 1 < nkt) {
            int k0 = (t + 1) * TBK;
#pragma unroll
            for (int it = 0; it < 2; it++) {
                int idx = tid + it * 256;
                int r = idx >> 2, kq = (idx & 3) * 4;
                int gr = row0 + r;
                aR[it] = make_float4(0.f, 0.f, 0.f, 0.f);
                if (gr < M) aR[it] = *(const float4*)(A + (size_t)gr * K + k0 + kq);
                int k = idx >> 5, cq = (idx & 31) * 4;
                bR[it] = *(const float4*)(B + (size_t)(k0 + k) * N + cq);
            }
        }
        const int buf = t & 1;
#pragma unroll
        for (int ks = 0; ks < TBK; ks += 8) {
            unsigned af[4][4], bf[4][2];
#pragma unroll
            for (int mt = 0; mt < 4; mt++) {
                int r = wm0 + mt * 16 + lr;
                int c = ks + lc;
                af[mt][0] = As[buf][c][r];
                af[mt][1] = As[buf][c][r + 8];
                af[mt][2] = As[buf][c + 4][r];
                af[mt][3] = As[buf][c + 4][r + 8];
            }
#pragma unroll
            for (int nt = 0; nt < 4; nt++) {
                int n = wn0 + nt * 8 + lr;
                int k = ks + lc;
                bf[nt][0] = Bs[buf][k][n];
                bf[nt][1] = Bs[buf][k + 4][n];
            }
#pragma unroll
            for (int mt = 0; mt < 4; mt++)
#pragma unroll
                for (int nt = 0; nt < 4; nt++) {
                    float* d = acc[mt][nt];
                    asm volatile(
                        "mma.sync.aligned.m16n8k8.row.col.f32.tf32.tf32.f32 "
                        "{%0,%1,%2,%3}, {%4,%5,%6,%7}, {%8,%9}, {%0,%1,%2,%3};\n"
                        : "+f"(d[0]), "+f"(d[1]), "+f"(d[2]), "+f"(d[3])
                        : "r"(af[mt][0]), "r"(af[mt][1]), "r"(af[mt][2]), "r"(af[mt][3]),
                          "r"(bf[nt][0]), "r"(bf[nt][1]));
                }
        }
        if (t + 1 < nkt) {
            const int nb = buf ^ 1;
#pragma unroll
            for (int it = 0; it < 2; it++) {
                int idx = tid + it * 256;
                int r = idx >> 2, kq = (idx & 3) * 4;
                As[nb][kq + 0][r] = f2tf(aR[it].x);
                As[nb][kq + 1][r] = f2tf(aR[it].y);
                As[nb][kq + 2][r] = f2tf(aR[it].z);
                As[nb][kq + 3][r] = f2tf(aR[it].w);
                int k = idx >> 5, cq = (idx & 31) * 4;
                Bs[nb][k][cq + 0] = f2tf(bR[it].x);
                Bs[nb][k][cq + 1] = f2tf(bR[it].y);
                Bs[nb][k][cq + 2] = f2tf(bR[it].z);
                Bs[nb][k][cq + 3] = f2tf(bR[it].w);
            }
            __syncthreads();
        }
    }
    float* C = p.C;
#pragma unroll
    for (int mt = 0; mt < 4; mt++) {
#pragma unroll
        for (int half = 0; half < 2; half++) {
            int gr = row0 + wm0 + mt * 16 + lr + half * 8;
            if (gr < M) {
#pragma unroll
                for (int nt = 0; nt < 4; nt++) {
                    float2 v = half ? make_float2(acc[mt][nt][2], acc[mt][nt][3])
                                    : make_float2(acc[mt][nt][0], acc[mt][nt][1]);
                    *(float2*)(C + (size_t)gr * 128 + wn0 + nt * 8 + lc * 2) = v;
                }
            }
        }
    }
}

// ================= merged compose kernel (fp32, tiny) =================
// t in [0,512): Qu; [512,2560): Qm; [2560,35328): Bu/Bm; [35328,35360): cm/cu
__global__ void compose_all(const float* __restrict__ w1um_s, const float* __restrict__ a1um_s,
                            const float* __restrict__ w1mu_d, const float* __restrict__ a1mu_d,
                            const float* __restrict__ w1mu_s, const float* __restrict__ a1mu_s,
                            const float* __restrict__ w1um_d, const float* __restrict__ a1um_d,
                            const float* __restrict__ w2um_s, const float* __restrict__ a2um_s,
                            const float* __restrict__ w2mu_d, const float* __restrict__ a2mu_d,
                            const float* __restrict__ w2mu_s, const float* __restrict__ a2mu_s,
                            const float* __restrict__ w2um_d, const float* __restrict__ a2um_d,
                            const float* __restrict__ dw1,
                            const float* __restrict__ b2um, const float* __restrict__ b2mu,
                            float* __restrict__ Qu, float* __restrict__ Qm,
                            float* __restrict__ Bu, float* __restrict__ Bm,
                            float* __restrict__ cm, float* __restrict__ cu) {
    int t = blockIdx.x * blockDim.x + threadIdx.x;
    if (t < 512) {
        int k = t >> 4, j = t & 15, h = j & 7;
        const float* W = (j < 8) ? w1um_s : w1mu_d;
        const float* a = (j < 8) ? a1um_s : a1mu_d;
        float acc = 0.f;
        for (int c = 0; c < 16; c++) acc += W[k * 128 + h * 16 + c] * a[h * 16 + c];
        Qu[t] = acc;
    } else if (t < 2560) {
        int tt = t - 512;
        int k = tt >> 4, j = tt & 15, h = j & 7;
        const float* W = (j < 8) ? w1mu_s : w1um_d;
        const float* a = (j < 8) ? a1mu_s : a1um_d;
        float acc = 0.f;
        for (int c = 0; c < 16; c++) acc += W[k * 128 + h * 16 + c] * a[h * 16 + c];
        Qm[tt] = acc;
    } else if (t < 2560 + 32768) {
        int tb = t - 2560;
        int which = tb >> 14;
        int tt = tb & 16383;
        int k = tt >> 7, j = tt & 127;
        float acc = 0.f;
        if (which == 0) {
            if (j < 64) {
                int h = j >> 4, jj = j & 15;
                for (int i = 0; i < 128; i++)
                    acc += w2um_s[k * 512 + h * 128 + i] * dw1[(size_t)(512 + h * 128 + i) * 16 + jj];
            } else if (j < 68) {
                int h = j - 64;
                for (int c = 0; c < 128; c++) acc += w2um_s[k * 512 + h * 128 + c] * a2um_s[h * 128 + c];
            } else if (j < 72) {
                int h = j - 68;
                for (int c = 0; c < 128; c++) acc += w2mu_d[k * 512 + h * 128 + c] * a2mu_d[h * 128 + c];
            }
            Bu[tt] = acc;
        } else {
            if (j < 64) {
                int h = j >> 4, jj = j & 15;
                for (int i = 0; i < 128; i++)
                    acc += w2mu_s[k * 512 + h * 128 + i] * dw1[(size_t)(h * 128 + i) * 16 + jj];
            } else if (j < 68) {
                int h = j - 64;
                for (int c = 0; c < 128; c++) acc += w2mu_s[k * 512 + h * 128 + c] * a2mu_s[h * 128 + c];
            } else if (j < 72) {
                int h = j - 68;
                for (int c = 0; c < 128; c++) acc += w2um_d[k * 512 + h * 128 + c] * a2um_d[h * 128 + c];
            }
            Bm[tt] = acc;
        }
    } else if (t < 2560 + 32768 + 32) {
        int j = t - (2560 + 32768);
        if (j < 16) {
            float acc = 0.f;
            for (int i = 0; i < 512; i++) acc += b2um[i] * dw1[(size_t)(512 + i) * 16 + j];
            cm[j] = acc;
        } else {
            int jj = j - 16;
            float acc = 0.f;
            for (int i = 0; i < 512; i++) acc += b2mu[i] * dw1[(size_t)i * 16 + jj];
            cu[jj] = acc;
        }
    }
}

// ================= merged node scores: warp-per-node, both node types =================
template <int K>
__device__ __forceinline__ void score_node(const float* __restrict__ xr,
                                           const float* __restrict__ Q,
                                           float* __restrict__ sp_out, int lane) {
    float p[16];
#pragma unroll
    for (int j = 0; j < 16; j++) p[j] = 0.f;
#pragma unroll
    for (int kk = 0; kk < K / 32; kk++) {
        int k = kk * 32 + lane;
        float xv = xr[k];
        const float4* q4 = (const float4*)(Q + k * 16);
        float4 q0 = q4[0], q1 = q4[1], q2 = q4[2], q3 = q4[3];
        p[0] += xv * q0.x; p[1] += xv * q0.y; p[2]  += xv * q0.z; p[3]  += xv * q0.w;
        p[4] += xv * q1.x; p[5] += xv * q1.y; p[6]  += xv * q1.z; p[7]  += xv * q1.w;
        p[8] += xv * q2.x; p[9] += xv * q2.y; p[10] += xv * q2.z; p[11] += xv * q2.w;
        p[12]+= xv * q3.x; p[13]+= xv * q3.y; p[14] += xv * q3.z; p[15] += xv * q3.w;
    }
#pragma unroll
    for (int j = 0; j < 16; j++)
#pragma unroll
        for (int o = 16; o; o >>= 1) p[j] += __shfl_xor_sync(0xffffffffu, p[j], o);
    if (lane == 0) {
        float4* sp = (float4*)sp_out;
        sp[0] = make_float4(p[0], p[1], p[2], p[3]);
        sp[1] = make_float4(p[4], p[5], p[6], p[7]);
        sp[2] = make_float4(p[8], p[9], p[10], p[11]);
        sp[3] = make_float4(p[12], p[13], p[14], p[15]);
    }
}

__global__ void score_both(const float* __restrict__ xu, const float* __restrict__ Qu,
                           float* __restrict__ s1u,
                           const float* __restrict__ xm, const float* __restrict__ Qm,
                           float* __restrict__ s1m) {
    int warp = (blockIdx.x * blockDim.x + threadIdx.x) >> 5;
    int lane = threadIdx.x & 31;
    if (warp < NU) {
        score_node<32>(xu + (size_t)warp * 32, Qu, s1u + (size_t)warp * 16, lane);
    } else if (warp < NU + NM) {
        int n = warp - NU;
        score_node<128>(xm + (size_t)n * 128, Qm, s1m + (size_t)n * 16, lane);
    }
}

// ================= CSR build (add_off folded away; consumers add bsum[d>>10]) ========
__global__ void zero_int(int* __restrict__ p, int n) {
    int i = blockIdx.x * blockDim.x + threadIdx.x;
    if (i < n) p[i] = 0;
}
__global__ void count2_k(const int* __restrict__ um_dst, const int* __restrict__ mu_dst,
                         int* __restrict__ cnt) {
    int i = blockIdx.x * blockDim.x + threadIdx.x;
    if (i >= 2 * NE) return;
    int d = (i < NE) ? um_dst[i] : (NM + mu_dst[i - NE]);
    atomicAdd(&cnt[d], 1);
}
// scan within block; also zeroes cnt for reuse as 'cur' by scatter
__global__ void scan_block(int* __restrict__ cnt, int* __restrict__ row,
                           int* __restrict__ bsum, int n) {
    __shared__ int sh[1024];
    int i = blockIdx.x * 1024 + threadIdx.x;
    int v = (i < n) ? cnt[i] : 0;
    sh[threadIdx.x] = v;
    __syncthreads();
    for (int o = 1; o < 1024; o <<= 1) {
        int t = (threadIdx.x >= o) ? sh[threadIdx.x - o] : 0;
        __syncthreads();
        sh[threadIdx.x] += t;
        __syncthreads();
    }
    if (i < n) { row[i] = sh[threadIdx.x] - v; cnt[i] = 0; }
    if (threadIdx.x == 1023) bsum[blockIdx.x] = sh[1023];
}
__global__ void scan_bsum(int* __restrict__ bsum, int nb) {
    __shared__ int sh[128];
    int t = threadIdx.x;
    int v = (t < nb) ? bsum[t] : 0;
    sh[t] = v;
    __syncthreads();
    for (int o = 1; o < 128; o <<= 1) {
        int x = (t >= o) ? sh[t - o] : 0;
        __syncthreads();
        sh[t] += x;
        __syncthreads();
    }
    if (t < nb) bsum[t] = sh[t] - v;
}
__global__ void scatter2_k(const int* __restrict__ um_src, const int* __restrict__ um_dst,
                           const int* __restrict__ mu_src, const int* __restrict__ mu_dst,
                           const int* __restrict__ row, const int* __restrict__ bsum,
                           int* __restrict__ cur, int* __restrict__ ssrc) {
    int i = blockIdx.x * blockDim.x + threadIdx.x;
    if (i >= 2 * NE) return;
    int d, s;
    if (i < NE) { d = um_dst[i]; s = um_src[i]; }
    else        { d = NM + mu_dst[i - NE]; s = mu_src[i - NE]; }
    int pos = row[d] + bsum[d >> 10] + atomicAdd(&cur[d], 1);
    ssrc[pos] = s;
}

// ================= L1 um: per-head raw aggregation + fused 32->16 transform ==========
__global__ void __launch_bounds__(256)
agg1_um(const float* __restrict__ xu, const float* __restrict__ s1u,
        const float* __restrict__ s1m, const float* __restrict__ w1um_s,
        const float* __restrict__ b1um, float* __restrict__ zm1,
        const int* __restrict__ row, const int* __restrict__ deg_,
        const int* __restrict__ bsum, const int* __restrict__ ssrc) {
    int d = blockIdx.x;
    int h = threadIdx.x >> 5;
    int k = threadIdx.x & 31;
    int start = row[d] + bsum[d >> 10];
    int deg = deg_[d];
    const int* sp = ssrc + start;
    float sdd = s1m[d * 16 + 8 + h];
    float acc = 0.f, se = 0.f;
    for (int e = 0; e < deg; e++) {
        int s = sp[e];
        float v = s1u[s * 16 + h] + sdd;
        v = (v > 0.f) ? v : 0.2f * v;
        float w = __expf(v);
        se += w;
        acc += w * xu[(size_t)s * FU + k];
    }
    float agg = acc / (se + 1e-16f);
    const float4* w4 = (const float4*)(w1um_s + k * 128 + h * 16);
    float4 w0 = w4[0], w1 = w4[1], w2 = w4[2], w3 = w4[3];
    float p[16];
    p[0] = agg * w0.x; p[1] = agg * w0.y; p[2]  = agg * w0.z; p[3]  = agg * w0.w;
    p[4] = agg * w1.x; p[5] = agg * w1.y; p[6]  = agg * w1.z; p[7]  = agg * w1.w;
    p[8] = agg * w2.x; p[9] = agg * w2.y; p[10] = agg * w2.z; p[11] = agg * w2.w;
    p[12]= agg * w3.x; p[13]= agg * w3.y; p[14] = agg * w3.z; p[15] = agg * w3.w;
#pragma unroll
    for (int j = 0; j < 16; j++)
#pragma unroll
        for (int o = 16; o; o >>= 1) p[j] += __shfl_xor_sync(0xffffffffu, p[j], o);
    if (k == 0) {
        float* out = zm1 + (size_t)d * 128 + h * 16;
        const float* b = b1um + h * 16;
#pragma unroll
        for (int j = 0; j < 16; j++) out[j] = fmaxf(p[j] + b[j], 0.f);
    }
}

// ================= L1 mu: standard D=128 aggregation over hs_mu1 =================
__global__ void __launch_bounds__(128)
agg1_mu(const float* __restrict__ hs, const float* __restrict__ s1m,
        const float* __restrict__ s1u, const float* __restrict__ b1mu,
        float* __restrict__ zu1, const int* __restrict__ row,
        const int* __restrict__ deg_, const int* __restrict__ bsum,
        const int* __restrict__ ssrc) {
    int d = blockIdx.x;           // user index
    int bucket = NM + d;          // global CSR bucket
    int tid = threadIdx.x;
    int h = tid >> 4;
    int start = row[bucket] + bsum[bucket >> 10];
    int deg = deg_[bucket];
    const int* sp = ssrc + start;
    float sdd = s1u[d * 16 + 8 + h];
    float acc = 0.f, se = 0.f;
#pragma unroll 4
    for (int e = 0; e < deg; e++) {
        int s = sp[e];
        float v = s1m[s * 16 + h] + sdd;
        v = (v > 0.f) ? v : 0.2f * v;
        float w = __expf(v);
        se += w;
        acc += w * hs[(size_t)s * 128 + tid];
    }
    zu1[(size_t)d * 128 + tid] = fmaxf(acc / (se + 1e-16f) + b1mu[tid], 0.f);
}

// ================= L2: fused aggregation + decoder pre (both directions) =============
__global__ void __launch_bounds__(64)
agg2(const float* __restrict__ Pu, const float* __restrict__ Pm,
     const float* __restrict__ cm, const float* __restrict__ cu,
     float* __restrict__ prem, float* __restrict__ preu,
     const int* __restrict__ row, const int* __restrict__ deg_,
     const int* __restrict__ bsum, const int* __restrict__ ssrc) {
    __shared__ float red[16];
    int d = blockIdx.x;
    const float *Psrc, *Pdrow, *c; float* out; int ld;
    if (d < NM) { Psrc = Pu; c = cm; out = prem; ld = d;      Pdrow = Pm + (size_t)d * 128; }
    else        { Psrc = Pm; c = cu; out = preu; ld = d - NM; Pdrow = Pu + (size_t)ld * 128; }
    int t = threadIdx.x;
    int h = t >> 4, jj = t & 15;
    int start = row[d] + bsum[d >> 10];
    int deg = deg_[d];
    const int* sp = ssrc + start;
    float sdd = Pdrow[68 + h];
    float acc = 0.f, se = 0.f;
#pragma unroll 2
    for (int e = 0; e < deg; e++) {
        int s = sp[e];
        const float* pr = Psrc + (size_t)s * 128;
        float v = pr[64 + h] + sdd;
        v = (v > 0.f) ? v : 0.2f * v;
        float w = __expf(v);
        se += w;
        acc += w * pr[t];
    }
    float val = acc / (se + 1e-16f);
    if (t < 16) red[t] = 0.f;
    __syncthreads();
    atomicAdd(&red[jj], val);
    __syncthreads();
    if (t < 16) out[(size_t)ld * 16 + t] = red[t] + c[t];
}

// ================= decoder final =================
__global__ void dec_final(const float* __restrict__ preu, const float* __restrict__ prem,
                          const int* __restrict__ lu, const int* __restrict__ lm,
                          const float* __restrict__ db1, const float* __restrict__ dw2,
                          const float* __restrict__ db2, float* __restrict__ out, int EL) {
    int i = blockIdx.x * blockDim.x + threadIdx.x;
    if (i >= EL) return;
    const float* pu = preu + (size_t)lu[i] * 16;
    const float* pm = prem + (size_t)lm[i] * 16;
    float r = db2[0];
#pragma unroll
    for (int j = 0; j < 16; j++) {
        float h = fmaxf(pu[j] + pm[j] + db1[j], 0.f);
        r += h * dw2[j];
    }
    out[i] = r;
}

extern "C" void kernel_launch(void* const* d_in, const int* in_sizes, int n_in,
                              void* d_out, int out_size) {
    const float* xu     = (const float*)d_in[0];
    const float* xm     = (const float*)d_in[1];
    const int*   um_src = (const int*)d_in[2];
    const int*   um_dst = (const int*)d_in[3];
    const int*   mu_src = (const int*)d_in[4];
    const int*   mu_dst = (const int*)d_in[5];
    const int*   lab_u  = (const int*)d_in[6];
    const int*   lab_m  = (const int*)d_in[7];
    const float* w1um_s = (const float*)d_in[8];
    const float* w1um_d = (const float*)d_in[9];
    const float* a1um_s = (const float*)d_in[10];
    const float* a1um_d = (const float*)d_in[11];
    const float* b1um   = (const float*)d_in[12];
    const float* w1mu_s = (const float*)d_in[13];
    const float* w1mu_d = (const float*)d_in[14];
    const float* a1mu_s = (const float*)d_in[15];
    const float* a1mu_d = (const float*)d_in[16];
    const float* b1mu   = (const float*)d_in[17];
    const float* w2um_s = (const float*)d_in[18];
    const float* w2um_d = (const float*)d_in[19];
    const float* a2um_s = (const float*)d_in[20];
    const float* a2um_d = (const float*)d_in[21];
    const float* b2um   = (const float*)d_in[22];
    const float* w2mu_s = (const float*)d_in[23];
    const float* w2mu_d = (const float*)d_in[24];
    const float* a2mu_s = (const float*)d_in[25];
    const float* a2mu_d = (const float*)d_in[26];
    const float* b2mu   = (const float*)d_in[27];
    const float* dw1    = (const float*)d_in[28];
    const float* db1    = (const float*)d_in[29];
    const float* dw2    = (const float*)d_in[30];
    const float* db2    = (const float*)d_in[31];

    float *ZU1, *ZM1, *HSMU1, *PU, *PM, *S1U, *S1M, *PREU, *PREM;
    float *QU, *QM, *BU, *BM, *CM, *CU;
    int *ROW, *CUR, *SSRC, *BSUM;
    cudaGetSymbolAddress((void**)&ZU1,   g_zu1);
    cudaGetSymbolAddress((void**)&ZM1,   g_zm1);
    cudaGetSymbolAddress((void**)&HSMU1, g_hsmu1);
    cudaGetSymbolAddress((void**)&PU,    g_Pu);
    cudaGetSymbolAddress((void**)&PM,    g_Pm);
    cudaGetSymbolAddress((void**)&S1U,   g_s1u);
    cudaGetSymbolAddress((void**)&S1M,   g_s1m);
    cudaGetSymbolAddress((void**)&PREU,  g_preu);
    cudaGetSymbolAddress((void**)&PREM,  g_prem);
    cudaGetSymbolAddress((void**)&QU,    g_Qu);
    cudaGetSymbolAddress((void**)&QM,    g_Qm);
    cudaGetSymbolAddress((void**)&BU,    g_Bu);
    cudaGetSymbolAddress((void**)&BM,    g_Bm);
    cudaGetSymbolAddress((void**)&CM,    g_cm);
    cudaGetSymbolAddress((void**)&CU,    g_cu);
    cudaGetSymbolAddress((void**)&ROW,   g_row);
    cudaGetSymbolAddress((void**)&CUR,   g_cur);
    cudaGetSymbolAddress((void**)&SSRC,  g_ssrc);
    cudaGetSymbolAddress((void**)&BSUM,  g_bsum);

    int nb = (NTOT + 1023) / 1024;

    // 1-3: CSR head
    zero_int<<<(NTOT + 255) / 256, 256>>>(CUR, NTOT);
    count2_k<<<(2 * NE + 255) / 256, 256>>>(um_dst, mu_dst, CUR);
    scan_block<<<nb, 1024>>>(CUR, ROW, BSUM, NTOT);   // also zeroes CUR

    // 4: hs GEMM (independent of CSR) — positioned here so ncu -s5-c1 profiles it
    {
        GP pa = { xm, w1mu_s, HSMU1, NM };
        dim3 grid(1, (NM + TBM - 1) / TBM, 1);
        gemm_dual<<<grid, 256>>>(pa, pa);
    }

    // 5-6: CSR tail
    scan_bsum<<<1, 128>>>(BSUM, nb);
    scatter2_k<<<(2 * NE + 255) / 256, 256>>>(um_src, um_dst, mu_src, mu_dst,
                                              ROW, BSUM, CUR, SSRC);

    // 7: weight compositions
    compose_all<<<(2560 + 32768 + 32 + 255) / 256, 256>>>(
        w1um_s, a1um_s, w1mu_d, a1mu_d, w1mu_s, a1mu_s, w1um_d, a1um_d,
        w2um_s, a2um_s, w2mu_d, a2mu_d, w2mu_s, a2mu_s, w2um_d, a2um_d,
        dw1, b2um, b2mu, QU, QM, BU, BM, CM, CU);

    // 8: layer-1 node scores (both types, one launch)
    score_both<<<((NU + NM) * 32 + 255) / 256, 256>>>(xu, QU, S1U, xm, QM, S1M);

    // 9-10: layer-1 aggregation
    agg1_um<<<NM, 256>>>(xu, S1U, S1M, w1um_s, b1um, ZM1, ROW, CUR, BSUM, SSRC);
    agg1_mu<<<NU, 128>>>(HSMU1, S1M, S1U, b1mu, ZU1, ROW, CUR, BSUM, SSRC);

    // 11: layer-2 projections
    {
        GP p0 = { ZU1, BU, PU, NU };
        GP p1 = { ZM1, BM, PM, NM };
        dim3 grid(1, (NU + TBM - 1) / TBM, 2);
        gemm_dual<<<grid, 256>>>(p0, p1);
    }

    // 12: layer-2 aggregation fused with decoder pre-projection
    agg2<<<NTOT, 64>>>(PU, PM, CM, CU, PREM, PREU, ROW, CUR, BSUM, SSRC);

    // 13: decoder final
    dec_final<<<(NEL + 255) / 256, 256>>>(PREU, PREM, lab_u, lab_m,
                                          db1, dw2, db2, (float*)d_out, NEL);
}